// round 13
// baseline (speedup 1.0000x reference)
#include <cuda_runtime.h>

// ---------------------------------------------------------------------------
// AttentionBlock (fp32 MHA): pproc(x,W,b) == x@W.T + b exactly in fwd pass.
// B=4, S=2048, H=1024, NH=16, HD=64. No scaling, no mask.
// Output buffer = [out (B,S,H)] ++ [probs (B,NH,S,S)], fp32.
//
// R9 version: double-buffered software-pipelined FFMA2 GEMMs (1 sync/iter,
// global prefetch overlapped with compute), softmax fused away:
//   scores writes exp(s-12) + deterministic partial row sums,
//   tiny kernel produces 1/rowsum,
//   ctx normalizes P at load time and writes normalized probs back in place.
// ---------------------------------------------------------------------------

namespace {
constexpr int B_  = 4;
constexpr int S_  = 2048;
constexpr int H_  = 1024;
constexpr int NH_ = 16;
constexpr int HD_ = 64;
constexpr int M_  = B_ * S_;          // 8192
constexpr int BH_ = B_ * NH_;         // 64
constexpr long long OUT_ELEMS   = (long long)M_ * H_;
constexpr long long PROBS_ELEMS = (long long)BH_ * S_ * S_;
}

// Scratch (device globals)
__device__ float g_q[M_ * H_];            // [BH][S][HD]
__device__ float g_k[M_ * H_];
__device__ float g_v[M_ * H_];
__device__ float g_ctx[M_ * H_];          // [B,S,H]
__device__ float g_psum[(long long)BH_ * S_ * 16];   // per-(row, n-tile) exp sums
__device__ float g_inv[BH_ * S_];         // 1 / row sum
__device__ float g_probs_fallback[268435456];

// ---------------- packed f32x2 FMA helpers --------------------------------
typedef unsigned long long u64;

__device__ __forceinline__ u64 pk2(float lo, float hi) {
    u64 r;
    asm("mov.b64 %0, {%1, %2};" : "=l"(r) : "f"(lo), "f"(hi));
    return r;
}
__device__ __forceinline__ void fma2(u64& d, u64 a, u64 b) {
    asm("fma.rn.f32x2 %0, %1, %2, %0;" : "+l"(d) : "l"(a), "l"(b));
}
__device__ __forceinline__ float2 up2(u64 v) {
    float2 r;
    asm("mov.b64 {%0, %1}, %2;" : "=f"(r.x), "=f"(r.y) : "l"(v));
    return r;
}

// ---------------------------------------------------------------------------
// Kernel 1: fused QKV projections (grid.z selects Q/K/V).
// C[m,n] = sum_k X[m,k] W[n,k] + bias[n], written as [BH][S][HD].
// 128x128 tile, BK=16, 256 threads, 8x8 per thread (cols n = p*32 + tx*2).
// ---------------------------------------------------------------------------
__global__ void __launch_bounds__(256, 2) proj_qkv_kernel(
    const float* __restrict__ X,
    const float* __restrict__ Wq, const float* __restrict__ Bq,
    const float* __restrict__ Wk, const float* __restrict__ Bk,
    const float* __restrict__ Wv, const float* __restrict__ Bv)
{
    const int sel = blockIdx.z;
    const float* W    = (sel == 0) ? Wq : (sel == 1) ? Wk : Wv;
    const float* bias = (sel == 0) ? Bq : (sel == 1) ? Bk : Bv;
    float* out        = (sel == 0) ? g_q : (sel == 1) ? g_k : g_v;

    constexpr int LDA = 132;
    __shared__ __align__(16) float As[2][16 * LDA];
    __shared__ __align__(16) float Bs[2][16 * LDA];

    const int tid = threadIdx.x;
    const int n0 = blockIdx.x * 128;
    const int m0 = blockIdx.y * 128;
    const int tx = tid & 15;
    const int ty = tid >> 4;
    const int lrow = tid >> 2;          // 0..63
    const int c4 = (tid & 3) * 4;

    const float* xA0 = X + (size_t)(m0 + lrow) * H_ + c4;
    const float* xA1 = xA0 + (size_t)64 * H_;
    const float* xB0 = W + (size_t)(n0 + lrow) * H_ + c4;
    const float* xB1 = xB0 + (size_t)64 * H_;

    u64 acc[8][4];
#pragma unroll
    for (int i = 0; i < 8; i++)
#pragma unroll
        for (int p = 0; p < 4; p++) acc[i][p] = 0ULL;

    float4 a0s = *(const float4*)(xA0);
    float4 a1s = *(const float4*)(xA1);
    float4 b0s = *(const float4*)(xB0);
    float4 b1s = *(const float4*)(xB1);

#define PROJ_STORE(BUF) do {                                               \
    float* as = &As[BUF][0]; float* bs = &Bs[BUF][0];                      \
    as[(c4+0)*LDA + lrow]      = a0s.x; as[(c4+1)*LDA + lrow]      = a0s.y;\
    as[(c4+2)*LDA + lrow]      = a0s.z; as[(c4+3)*LDA + lrow]      = a0s.w;\
    as[(c4+0)*LDA + lrow + 64] = a1s.x; as[(c4+1)*LDA + lrow + 64] = a1s.y;\
    as[(c4+2)*LDA + lrow + 64] = a1s.z; as[(c4+3)*LDA + lrow + 64] = a1s.w;\
    bs[(c4+0)*LDA + lrow]      = b0s.x; bs[(c4+1)*LDA + lrow]      = b0s.y;\
    bs[(c4+2)*LDA + lrow]      = b0s.z; bs[(c4+3)*LDA + lrow]      = b0s.w;\
    bs[(c4+0)*LDA + lrow + 64] = b1s.x; bs[(c4+1)*LDA + lrow + 64] = b1s.y;\
    bs[(c4+2)*LDA + lrow + 64] = b1s.z; bs[(c4+3)*LDA + lrow + 64] = b1s.w;\
} while (0)

    PROJ_STORE(0);
    __syncthreads();

    for (int it = 0; it < 64; it++) {
        const int buf = it & 1;
        if (it < 63) {
            const int k0 = (it + 1) * 16;
            a0s = *(const float4*)(xA0 + k0);
            a1s = *(const float4*)(xA1 + k0);
            b0s = *(const float4*)(xB0 + k0);
            b1s = *(const float4*)(xB1 + k0);
        }
#pragma unroll
        for (int kk = 0; kk < 16; kk++) {
            const float* as = &As[buf][kk * LDA];
            const float* bs = &Bs[buf][kk * LDA];
            float4 a0 = *(const float4*)(as + ty * 8);
            float4 a1 = *(const float4*)(as + ty * 8 + 4);
            u64 ad[8];
            ad[0] = pk2(a0.x, a0.x); ad[1] = pk2(a0.y, a0.y);
            ad[2] = pk2(a0.z, a0.z); ad[3] = pk2(a0.w, a0.w);
            ad[4] = pk2(a1.x, a1.x); ad[5] = pk2(a1.y, a1.y);
            ad[6] = pk2(a1.z, a1.z); ad[7] = pk2(a1.w, a1.w);
            u64 b0 = *(const u64*)(bs + 0 * 32 + tx * 2);
            u64 b1 = *(const u64*)(bs + 1 * 32 + tx * 2);
            u64 b2 = *(const u64*)(bs + 2 * 32 + tx * 2);
            u64 b3 = *(const u64*)(bs + 3 * 32 + tx * 2);
#pragma unroll
            for (int i = 0; i < 8; i++) {
                fma2(acc[i][0], ad[i], b0);
                fma2(acc[i][1], ad[i], b1);
                fma2(acc[i][2], ad[i], b2);
                fma2(acc[i][3], ad[i], b3);
            }
        }
        if (it < 63) PROJ_STORE(buf ^ 1);
        __syncthreads();
    }

#pragma unroll
    for (int i = 0; i < 8; i++) {
        const int m = m0 + ty * 8 + i;
        const int b = m >> 11;
        const int s = m & (S_ - 1);
#pragma unroll
        for (int p = 0; p < 4; p++) {
            float2 v = up2(acc[i][p]);
            const int n = n0 + p * 32 + tx * 2;
            float2 bb = *(const float2*)(bias + n);
            v.x += bb.x; v.y += bb.y;
            const int h = n >> 6, d = n & 63;
            *(float2*)(out + ((size_t)((b * NH_ + h) * S_ + s)) * HD_ + d) = v;
        }
    }
#undef PROJ_STORE
}

// ---------------------------------------------------------------------------
// Kernel 2: scores per (b,h): exp(Q K^T - 12) -> probs (unnormalized) plus
// deterministic per-(row, n-tile) partial sums.
// ---------------------------------------------------------------------------
__global__ void __launch_bounds__(256, 2) scores_kernel(float* __restrict__ probs)
{
    constexpr int LDA = 132;
    __shared__ __align__(16) float As[2][16 * LDA];
    __shared__ __align__(16) float Bs[2][16 * LDA];

    const int tid = threadIdx.x;
    const int n0 = blockIdx.x * 128;
    const int m0 = blockIdx.y * 128;
    const int bh = blockIdx.z;
    const float* Q = g_q + (size_t)bh * S_ * HD_;
    const float* K = g_k + (size_t)bh * S_ * HD_;

    const int tx = tid & 15;
    const int ty = tid >> 4;
    const int lrow = tid >> 2;
    const int c4 = (tid & 3) * 4;

    const float* xA0 = Q + (size_t)(m0 + lrow) * HD_ + c4;
    const float* xA1 = xA0 + (size_t)64 * HD_;
    const float* xB0 = K + (size_t)(n0 + lrow) * HD_ + c4;
    const float* xB1 = xB0 + (size_t)64 * HD_;

    u64 acc[8][4];
#pragma unroll
    for (int i = 0; i < 8; i++)
#pragma unroll
        for (int p = 0; p < 4; p++) acc[i][p] = 0ULL;

    float4 a0s = *(const float4*)(xA0);
    float4 a1s = *(const float4*)(xA1);
    float4 b0s = *(const float4*)(xB0);
    float4 b1s = *(const float4*)(xB1);

#define SC_STORE(BUF) do {                                                 \
    float* as = &As[BUF][0]; float* bs = &Bs[BUF][0];                      \
    as[(c4+0)*LDA + lrow]      = a0s.x; as[(c4+1)*LDA + lrow]      = a0s.y;\
    as[(c4+2)*LDA + lrow]      = a0s.z; as[(c4+3)*LDA + lrow]      = a0s.w;\
    as[(c4+0)*LDA + lrow + 64] = a1s.x; as[(c4+1)*LDA + lrow + 64] = a1s.y;\
    as[(c4+2)*LDA + lrow + 64] = a1s.z; as[(c4+3)*LDA + lrow + 64] = a1s.w;\
    bs[(c4+0)*LDA + lrow]      = b0s.x; bs[(c4+1)*LDA + lrow]      = b0s.y;\
    bs[(c4+2)*LDA + lrow]      = b0s.z; bs[(c4+3)*LDA + lrow]      = b0s.w;\
    bs[(c4+0)*LDA + lrow + 64] = b1s.x; bs[(c4+1)*LDA + lrow + 64] = b1s.y;\
    bs[(c4+2)*LDA + lrow + 64] = b1s.z; bs[(c4+3)*LDA + lrow + 64] = b1s.w;\
} while (0)

    SC_STORE(0);
    __syncthreads();

    for (int it = 0; it < 4; it++) {
        const int buf = it & 1;
        if (it < 3) {
            const int k0 = (it + 1) * 16;
            a0s = *(const float4*)(xA0 + k0);
            a1s = *(const float4*)(xA1 + k0);
            b0s = *(const float4*)(xB0 + k0);
            b1s = *(const float4*)(xB1 + k0);
        }
#pragma unroll
        for (int kk = 0; kk < 16; kk++) {
            const float* as = &As[buf][kk * LDA];
            const float* bs = &Bs[buf][kk * LDA];
            float4 a0 = *(const float4*)(as + ty * 8);
            float4 a1 = *(const float4*)(as + ty * 8 + 4);
            u64 ad[8];
            ad[0] = pk2(a0.x, a0.x); ad[1] = pk2(a0.y, a0.y);
            ad[2] = pk2(a0.z, a0.z); ad[3] = pk2(a0.w, a0.w);
            ad[4] = pk2(a1.x, a1.x); ad[5] = pk2(a1.y, a1.y);
            ad[6] = pk2(a1.z, a1.z); ad[7] = pk2(a1.w, a1.w);
            u64 b0 = *(const u64*)(bs + 0 * 32 + tx * 2);
            u64 b1 = *(const u64*)(bs + 1 * 32 + tx * 2);
            u64 b2 = *(const u64*)(bs + 2 * 32 + tx * 2);
            u64 b3 = *(const u64*)(bs + 3 * 32 + tx * 2);
#pragma unroll
            for (int i = 0; i < 8; i++) {
                fma2(acc[i][0], ad[i], b0);
                fma2(acc[i][1], ad[i], b1);
                fma2(acc[i][2], ad[i], b2);
                fma2(acc[i][3], ad[i], b3);
            }
        }
        if (it < 3) SC_STORE(buf ^ 1);
        __syncthreads();
    }

    // epilogue: exp(s - 12), store unnormalized, partial row sums
    float* P = probs + (size_t)bh * S_ * S_;
#pragma unroll
    for (int i = 0; i < 8; i++) {
        const int m = m0 + ty * 8 + i;
        float rs = 0.f;
#pragma unroll
        for (int p = 0; p < 4; p++) {
            float2 v = up2(acc[i][p]);
            v.x = __expf(v.x - 12.0f);
            v.y = __expf(v.y - 12.0f);
            rs += v.x + v.y;
            *(float2*)(P + (size_t)m * S_ + n0 + p * 32 + tx * 2) = v;
        }
        // reduce across the 16 tx lanes (xor offsets stay within 16-lane group)
#pragma unroll
        for (int o = 8; o; o >>= 1) rs += __shfl_xor_sync(0xffffffffu, rs, o);
        if (tx == 0)
            g_psum[((size_t)bh * S_ + m) * 16 + blockIdx.x] = rs;
    }
#undef SC_STORE
}

// ---------------------------------------------------------------------------
// Kernel 3: 1/rowsum (deterministic, 16 partials per row).
// ---------------------------------------------------------------------------
__global__ void __launch_bounds__(256) rsum_kernel()
{
    const int r = blockIdx.x * 256 + threadIdx.x;   // < 131072
    const float4* p = (const float4*)(g_psum + (size_t)r * 16);
    float4 a = p[0], b = p[1], c = p[2], d = p[3];
    float s = ((a.x + a.y) + (a.z + a.w)) + ((b.x + b.y) + (b.z + b.w))
            + ((c.x + c.y) + (c.z + c.w)) + ((d.x + d.y) + (d.z + d.w));
    g_inv[r] = 1.0f / s;
}

// ---------------------------------------------------------------------------
// Kernel 4: ctx = P_norm @ V per (b,h); P is normalized at load time and the
// normalized probs are written back in place. Tile 256x64, BK=16, 256 thr.
// ---------------------------------------------------------------------------
__global__ void __launch_bounds__(256, 2) ctx_kernel(float* __restrict__ probs)
{
    constexpr int LDA = 260;
    constexpr int LDB = 68;
    __shared__ __align__(16) float As[2][16 * LDA];
    __shared__ __align__(16) float Bs[2][16 * LDB];

    const int tid = threadIdx.x;
    const int tx = tid & 7;
    const int ty = tid >> 3;
    const int m0 = blockIdx.x * 256;
    const int bh = blockIdx.y;
    float* P = probs + (size_t)bh * S_ * S_;
    const float* V = g_v + (size_t)bh * S_ * HD_;

    const int lrow = tid >> 2;          // 0..63
    const int c4 = (tid & 3) * 4;

    float iv[4];
    float* pA[4];
#pragma unroll
    for (int t = 0; t < 4; t++) {
        const int r = m0 + lrow + t * 64;
        iv[t] = g_inv[bh * S_ + r];
        pA[t] = P + (size_t)r * S_ + c4;
    }
    const int jr = tid >> 4;
    const int dc = (tid & 15) * 4;
    const float* pB = V + (size_t)jr * HD_ + dc;

    u64 acc[8][4];
#pragma unroll
    for (int i = 0; i < 8; i++)
#pragma unroll
        for (int p = 0; p < 4; p++) acc[i][p] = 0ULL;

    float4 a_s[4];
    float4 b_s;
#pragma unroll
    for (int t = 0; t < 4; t++) {
        float4 v = *(const float4*)(pA[t]);
        v.x *= iv[t]; v.y *= iv[t]; v.z *= iv[t]; v.w *= iv[t];
        *(float4*)(pA[t]) = v;          // write back normalized probs
        a_s[t] = v;
    }
    b_s = *(const float4*)(pB);

#define CTX_STORE(BUF) do {                                                \
    float* as = &As[BUF][0];                                               \
    _Pragma("unroll")                                                      \
    for (int t = 0; t < 4; t++) {                                          \
        as[(c4+0)*LDA + lrow + t*64] = a_s[t].x;                           \
        as[(c4+1)*LDA + lrow + t*64] = a_s[t].y;                           \
        as[(c4+2)*LDA + lrow + t*64] = a_s[t].z;                           \
        as[(c4+3)*LDA + lrow + t*64] = a_s[t].w;                           \
    }                                                                      \
    *(float4*)(&Bs[BUF][jr * LDB + dc]) = b_s;                             \
} while (0)

    CTX_STORE(0);
    __syncthreads();

    for (int it = 0; it < 128; it++) {
        const int buf = it & 1;
        if (it < 127) {
            const int k0 = (it + 1) * 16;
#pragma unroll
            for (int t = 0; t < 4; t++) {
                float4 v = *(const float4*)(pA[t] + k0);
                v.x *= iv[t]; v.y *= iv[t]; v.z *= iv[t]; v.w *= iv[t];
                *(float4*)(pA[t] + k0) = v;
                a_s[t] = v;
            }
            b_s = *(const float4*)(pB + (size_t)k0 * HD_);
        }
#pragma unroll
        for (int kk = 0; kk < 16; kk++) {
            const float* as = &As[buf][kk * LDA];
            const float* bs = &Bs[buf][kk * LDB];
            float4 a0 = *(const float4*)(as + ty * 8);
            float4 a1 = *(const float4*)(as + ty * 8 + 4);
            u64 ad[8];
            ad[0] = pk2(a0.x, a0.x); ad[1] = pk2(a0.y, a0.y);
            ad[2] = pk2(a0.z, a0.z); ad[3] = pk2(a0.w, a0.w);
            ad[4] = pk2(a1.x, a1.x); ad[5] = pk2(a1.y, a1.y);
            ad[6] = pk2(a1.z, a1.z); ad[7] = pk2(a1.w, a1.w);
            u64 b0 = *(const u64*)(bs + 0 * 16 + tx * 2);
            u64 b1 = *(const u64*)(bs + 1 * 16 + tx * 2);
            u64 b2 = *(const u64*)(bs + 2 * 16 + tx * 2);
            u64 b3 = *(const u64*)(bs + 3 * 16 + tx * 2);
#pragma unroll
            for (int i = 0; i < 8; i++) {
                fma2(acc[i][0], ad[i], b0);
                fma2(acc[i][1], ad[i], b1);
                fma2(acc[i][2], ad[i], b2);
                fma2(acc[i][3], ad[i], b3);
            }
        }
        if (it < 127) CTX_STORE(buf ^ 1);
        __syncthreads();
    }

    const int b = bh >> 4;
    const int h = bh & 15;
#pragma unroll
    for (int i = 0; i < 8; i++) {
        const int s = m0 + ty * 8 + i;
#pragma unroll
        for (int p = 0; p < 4; p++) {
            float2 v = up2(acc[i][p]);
            const int d = p * 16 + tx * 2;
            *(float2*)(g_ctx + ((size_t)(b * S_ + s)) * H_ + h * HD_ + d) = v;
        }
    }
#undef CTX_STORE
}

// ---------------------------------------------------------------------------
// Kernel 5: out[m,n] = sum_k ctx[m,k] Wo[n,k] + bo[n] + hidden[m,n]
// ---------------------------------------------------------------------------
__global__ void __launch_bounds__(256, 2) outproj_kernel(
    const float* __restrict__ W,
    const float* __restrict__ bias,
    const float* __restrict__ hid,
    float* __restrict__ out)
{
    constexpr int LDA = 132;
    __shared__ __align__(16) float As[2][16 * LDA];
    __shared__ __align__(16) float Bs[2][16 * LDA];

    const int tid = threadIdx.x;
    const int n0 = blockIdx.x * 128;
    const int m0 = blockIdx.y * 128;
    const int tx = tid & 15;
    const int ty = tid >> 4;
    const int lrow = tid >> 2;
    const int c4 = (tid & 3) * 4;

    const float* xA0 = g_ctx + (size_t)(m0 + lrow) * H_ + c4;
    const float* xA1 = xA0 + (size_t)64 * H_;
    const float* xB0 = W + (size_t)(n0 + lrow) * H_ + c4;
    const float* xB1 = xB0 + (size_t)64 * H_;

    u64 acc[8][4];
#pragma unroll
    for (int i = 0; i < 8; i++)
#pragma unroll
        for (int p = 0; p < 4; p++) acc[i][p] = 0ULL;

    float4 a0s = *(const float4*)(xA0);
    float4 a1s = *(const float4*)(xA1);
    float4 b0s = *(const float4*)(xB0);
    float4 b1s = *(const float4*)(xB1);

#define OP_STORE(BUF) do {                                                 \
    float* as = &As[BUF][0]; float* bs = &Bs[BUF][0];                      \
    as[(c4+0)*LDA + lrow]      = a0s.x; as[(c4+1)*LDA + lrow]      = a0s.y;\
    as[(c4+2)*LDA + lrow]      = a0s.z; as[(c4+3)*LDA + lrow]      = a0s.w;\
    as[(c4+0)*LDA + lrow + 64] = a1s.x; as[(c4+1)*LDA + lrow + 64] = a1s.y;\
    as[(c4+2)*LDA + lrow + 64] = a1s.z; as[(c4+3)*LDA + lrow + 64] = a1s.w;\
    bs[(c4+0)*LDA + lrow]      = b0s.x; bs[(c4+1)*LDA + lrow]      = b0s.y;\
    bs[(c4+2)*LDA + lrow]      = b0s.z; bs[(c4+3)*LDA + lrow]      = b0s.w;\
    bs[(c4+0)*LDA + lrow + 64] = b1s.x; bs[(c4+1)*LDA + lrow + 64] = b1s.y;\
    bs[(c4+2)*LDA + lrow + 64] = b1s.z; bs[(c4+3)*LDA + lrow + 64] = b1s.w;\
} while (0)

    OP_STORE(0);
    __syncthreads();

    for (int it = 0; it < 64; it++) {
        const int buf = it & 1;
        if (it < 63) {
            const int k0 = (it + 1) * 16;
            a0s = *(const float4*)(xA0 + k0);
            a1s = *(const float4*)(xA1 + k0);
            b0s = *(const float4*)(xB0 + k0);
            b1s = *(const float4*)(xB1 + k0);
        }
#pragma unroll
        for (int kk = 0; kk < 16; kk++) {
            const float* as = &As[buf][kk * LDA];
            const float* bs = &Bs[buf][kk * LDA];
            float4 a0 = *(const float4*)(as + ty * 8);
            float4 a1 = *(const float4*)(as + ty * 8 + 4);
            u64 ad[8];
            ad[0] = pk2(a0.x, a0.x); ad[1] = pk2(a0.y, a0.y);
            ad[2] = pk2(a0.z, a0.z); ad[3] = pk2(a0.w, a0.w);
            ad[4] = pk2(a1.x, a1.x); ad[5] = pk2(a1.y, a1.y);
            ad[6] = pk2(a1.z, a1.z); ad[7] = pk2(a1.w, a1.w);
            u64 b0 = *(const u64*)(bs + 0 * 32 + tx * 2);
            u64 b1 = *(const u64*)(bs + 1 * 32 + tx * 2);
            u64 b2 = *(const u64*)(bs + 2 * 32 + tx * 2);
            u64 b3 = *(const u64*)(bs + 3 * 32 + tx * 2);
#pragma unroll
            for (int i = 0; i < 8; i++) {
                fma2(acc[i][0], ad[i], b0);
                fma2(acc[i][1], ad[i], b1);
                fma2(acc[i][2], ad[i], b2);
                fma2(acc[i][3], ad[i], b3);
            }
        }
        if (it < 63) OP_STORE(buf ^ 1);
        __syncthreads();
    }

#pragma unroll
    for (int i = 0; i < 8; i++) {
        const int m = m0 + ty * 8 + i;
#pragma unroll
        for (int p = 0; p < 4; p++) {
            float2 v = up2(acc[i][p]);
            const int n = n0 + p * 32 + tx * 2;
            float2 bb = *(const float2*)(bias + n);
            float2 hh = *(const float2*)(hid + (size_t)m * H_ + n);
            v.x += bb.x + hh.x;
            v.y += bb.y + hh.y;
            *(float2*)(out + (size_t)m * H_ + n) = v;
        }
    }
#undef OP_STORE
}

// ---------------------------------------------------------------------------
extern "C" void kernel_launch(void* const* d_in, const int* in_sizes, int n_in,
                              void* d_out, int out_size)
{
    (void)in_sizes; (void)n_in;

    const float* hs = (const float*)d_in[0];
    const float* Wq = (const float*)d_in[1];
    const float* bq = (const float*)d_in[2];
    const float* Wk = (const float*)d_in[3];
    const float* bk = (const float*)d_in[4];
    const float* Wv = (const float*)d_in[5];
    const float* bv = (const float*)d_in[6];
    const float* Wo = (const float*)d_in[7];
    const float* bo = (const float*)d_in[8];
    float* out = (float*)d_out;

    float* probs;
    if ((long long)out_size >= OUT_ELEMS + PROBS_ELEMS) {
        probs = out + OUT_ELEMS;
    } else {
        void* p = nullptr;
        cudaGetSymbolAddress(&p, g_probs_fallback);
        probs = (float*)p;
    }

    proj_qkv_kernel<<<dim3(H_ / 128, M_ / 128, 3), 256>>>(hs, Wq, bq, Wk, bk, Wv, bv);
    scores_kernel<<<dim3(S_ / 128, S_ / 128, BH_), 256>>>(probs);
    rsum_kernel<<<(BH_ * S_) / 256, 256>>>();
    ctx_kernel<<<dim3(S_ / 256, BH_), 256>>>(probs);
    outproj_kernel<<<dim3(H_ / 128, M_ / 128), 256>>>(Wo, bo, hs, out);
}

// round 15
// speedup vs baseline: 1.2536x; 1.2536x over previous
#include <cuda_runtime.h>
#include <cuda_bf16.h>

// ---------------------------------------------------------------------------
// AttentionBlock. pproc == plain linear in fwd. B=4,S=2048,H=1024,NH=16,HD=64.
// Output = [out (B,S,H)] ++ [probs (B,NH,S,S)], fp32.
// R14: scores + ctx via mma.sync bf16 (2-term split, 3 MMAs ~ fp32 GEMM).
//      tcgen05 is NOT available (harness PTX target is sm_103, not sm_103a).
// ---------------------------------------------------------------------------

namespace {
constexpr int B_  = 4;
constexpr int S_  = 2048;
constexpr int H_  = 1024;
constexpr int NH_ = 16;
constexpr int HD_ = 64;
constexpr int M_  = B_ * S_;
constexpr int BH_ = B_ * NH_;
constexpr long long OUT_ELEMS   = (long long)M_ * H_;
constexpr long long PROBS_ELEMS = (long long)BH_ * S_ * S_;

constexpr int SC_SMEM  = 68608;            // max(tiles 64K, stage 67584) + ps 1K
constexpr int CTX_SMEM = 512 + 2 * 49152;  // s_inv + 2 x (Phi|Plo|Vhi|Vlo)
}

typedef unsigned long long u64;
typedef __nv_bfloat16 bf16;

// ---------------- scratch ---------------------------------------------------
__device__ bf16  g_qhi[M_ * H_], g_qlo[M_ * H_];   // [BH][S][HD]
__device__ bf16  g_khi[M_ * H_], g_klo[M_ * H_];   // [BH][S][HD]
__device__ float g_v[M_ * H_];                     // [BH][S][HD]
__device__ bf16  g_vthi[M_ * H_], g_vtlo[M_ * H_]; // [BH][HD][S]
__device__ float g_ctx[M_ * H_];                   // [B,S,H]
__device__ float g_psum[(long long)BH_ * S_ * 16];
__device__ float g_inv[BH_ * S_];
__device__ float g_probs_fallback[268435456];

// ---------------- helpers ----------------------------------------------------
__device__ __forceinline__ unsigned smem_u32(const void* p) {
    unsigned a;
    asm("{ .reg .u64 t; cvta.to.shared.u64 t, %1; cvt.u32.u64 %0, t; }" : "=r"(a) : "l"(p));
    return a;
}
__device__ __forceinline__ unsigned sw128(unsigned off) { return off ^ ((off >> 3) & 0x70); }

// swizzled smem address of (row, kbyte) in a 128B-row tile
__device__ __forceinline__ unsigned swadr(unsigned base, int row, int kbyte) {
    unsigned off = (unsigned)(row * 128 + kbyte);
    return base + (off ^ ((off >> 3) & 0x70));
}
__device__ __forceinline__ void ldsm4(unsigned r[4], unsigned addr) {
    asm volatile("ldmatrix.sync.aligned.m8n8.x4.shared.b16 {%0,%1,%2,%3}, [%4];"
        : "=r"(r[0]), "=r"(r[1]), "=r"(r[2]), "=r"(r[3]) : "r"(addr));
}
__device__ __forceinline__ void mma16816(float d[4], const unsigned a[4], const unsigned b[2]) {
    asm volatile(
        "mma.sync.aligned.m16n8k16.row.col.f32.bf16.bf16.f32 "
        "{%0,%1,%2,%3}, {%4,%5,%6,%7}, {%8,%9}, {%0,%1,%2,%3};"
        : "+f"(d[0]), "+f"(d[1]), "+f"(d[2]), "+f"(d[3])
        : "r"(a[0]), "r"(a[1]), "r"(a[2]), "r"(a[3]), "r"(b[0]), "r"(b[1]));
}
__device__ __forceinline__ void split1(float x, bf16& h, bf16& l) {
    h = __float2bfloat16(x);
    l = __float2bfloat16(x - __bfloat162float(h));
}

// ---------------- packed f32x2 FMA helpers (proj/outproj) ------------------
__device__ __forceinline__ u64 pk2(float lo, float hi) {
    u64 r; asm("mov.b64 %0, {%1, %2};" : "=l"(r) : "f"(lo), "f"(hi)); return r;
}
__device__ __forceinline__ void fma2(u64& d, u64 a, u64 b) {
    asm("fma.rn.f32x2 %0, %1, %2, %0;" : "+l"(d) : "l"(a), "l"(b));
}
__device__ __forceinline__ float2 up2(u64 v) {
    float2 r; asm("mov.b64 {%0, %1}, %2;" : "=f"(r.x), "=f"(r.y) : "l"(v)); return r;
}

// ---------------------------------------------------------------------------
// Kernel 1: QKV projections (FFMA2). sel 0/1 -> bf16 split q/k; sel 2 -> fp32 v.
// ---------------------------------------------------------------------------
__global__ void __launch_bounds__(256, 2) proj_qkv_kernel(
    const float* __restrict__ X,
    const float* __restrict__ Wq, const float* __restrict__ Bq,
    const float* __restrict__ Wk, const float* __restrict__ Bk,
    const float* __restrict__ Wv, const float* __restrict__ Bv)
{
    const int sel = blockIdx.z;
    const float* W    = (sel == 0) ? Wq : (sel == 1) ? Wk : Wv;
    const float* bias = (sel == 0) ? Bq : (sel == 1) ? Bk : Bv;

    constexpr int LDA = 132;
    __shared__ __align__(16) float As[2][16 * LDA];
    __shared__ __align__(16) float Bs[2][16 * LDA];

    const int tid = threadIdx.x;
    const int n0 = blockIdx.x * 128, m0 = blockIdx.y * 128;
    const int tx = tid & 15, ty = tid >> 4;
    const int lrow = tid >> 2, c4 = (tid & 3) * 4;

    const float* xA0 = X + (size_t)(m0 + lrow) * H_ + c4;
    const float* xA1 = xA0 + (size_t)64 * H_;
    const float* xB0 = W + (size_t)(n0 + lrow) * H_ + c4;
    const float* xB1 = xB0 + (size_t)64 * H_;

    u64 acc[8][4];
#pragma unroll
    for (int i = 0; i < 8; i++)
#pragma unroll
        for (int p = 0; p < 4; p++) acc[i][p] = 0ULL;

    float4 a0s = *(const float4*)(xA0), a1s = *(const float4*)(xA1);
    float4 b0s = *(const float4*)(xB0), b1s = *(const float4*)(xB1);

#define PROJ_STORE(BUF) do {                                               \
    float* as = &As[BUF][0]; float* bs = &Bs[BUF][0];                      \
    as[(c4+0)*LDA + lrow]      = a0s.x; as[(c4+1)*LDA + lrow]      = a0s.y;\
    as[(c4+2)*LDA + lrow]      = a0s.z; as[(c4+3)*LDA + lrow]      = a0s.w;\
    as[(c4+0)*LDA + lrow + 64] = a1s.x; as[(c4+1)*LDA + lrow + 64] = a1s.y;\
    as[(c4+2)*LDA + lrow + 64] = a1s.z; as[(c4+3)*LDA + lrow + 64] = a1s.w;\
    bs[(c4+0)*LDA + lrow]      = b0s.x; bs[(c4+1)*LDA + lrow]      = b0s.y;\
    bs[(c4+2)*LDA + lrow]      = b0s.z; bs[(c4+3)*LDA + lrow]      = b0s.w;\
    bs[(c4+0)*LDA + lrow + 64] = b1s.x; bs[(c4+1)*LDA + lrow + 64] = b1s.y;\
    bs[(c4+2)*LDA + lrow + 64] = b1s.z; bs[(c4+3)*LDA + lrow + 64] = b1s.w;\
} while (0)

    PROJ_STORE(0);
    __syncthreads();

    for (int it = 0; it < 64; it++) {
        const int buf = it & 1;
        if (it < 63) {
            const int k0 = (it + 1) * 16;
            a0s = *(const float4*)(xA0 + k0); a1s = *(const float4*)(xA1 + k0);
            b0s = *(const float4*)(xB0 + k0); b1s = *(const float4*)(xB1 + k0);
        }
#pragma unroll
        for (int kk = 0; kk < 16; kk++) {
            const float* as = &As[buf][kk * LDA];
            const float* bs = &Bs[buf][kk * LDA];
            float4 a0 = *(const float4*)(as + ty * 8);
            float4 a1 = *(const float4*)(as + ty * 8 + 4);
            u64 ad[8];
            ad[0] = pk2(a0.x, a0.x); ad[1] = pk2(a0.y, a0.y);
            ad[2] = pk2(a0.z, a0.z); ad[3] = pk2(a0.w, a0.w);
            ad[4] = pk2(a1.x, a1.x); ad[5] = pk2(a1.y, a1.y);
            ad[6] = pk2(a1.z, a1.z); ad[7] = pk2(a1.w, a1.w);
            u64 b0 = *(const u64*)(bs + 0 * 32 + tx * 2);
            u64 b1 = *(const u64*)(bs + 1 * 32 + tx * 2);
            u64 b2 = *(const u64*)(bs + 2 * 32 + tx * 2);
            u64 b3 = *(const u64*)(bs + 3 * 32 + tx * 2);
#pragma unroll
            for (int i = 0; i < 8; i++) {
                fma2(acc[i][0], ad[i], b0); fma2(acc[i][1], ad[i], b1);
                fma2(acc[i][2], ad[i], b2); fma2(acc[i][3], ad[i], b3);
            }
        }
        if (it < 63) PROJ_STORE(buf ^ 1);
        __syncthreads();
    }
#undef PROJ_STORE

    bf16* dh = (sel == 0) ? g_qhi : g_khi;
    bf16* dl = (sel == 0) ? g_qlo : g_klo;
#pragma unroll
    for (int i = 0; i < 8; i++) {
        const int m = m0 + ty * 8 + i;
        const int b = m >> 11, s = m & (S_ - 1);
#pragma unroll
        for (int p = 0; p < 4; p++) {
            float2 v = up2(acc[i][p]);
            const int n = n0 + p * 32 + tx * 2;
            float2 bb = *(const float2*)(bias + n);
            v.x += bb.x; v.y += bb.y;
            const int h = n >> 6, d = n & 63;
            const size_t base = ((size_t)((b << 4) + h) * S_ + s) * HD_ + d;
            if (sel < 2) {
                bf16 h0, l0, h1, l1;
                split1(v.x, h0, l0); split1(v.y, h1, l1);
                __nv_bfloat162 hh; hh.x = h0; hh.y = h1;
                __nv_bfloat162 ll; ll.x = l0; ll.y = l1;
                *(__nv_bfloat162*)(dh + base) = hh;
                *(__nv_bfloat162*)(dl + base) = ll;
            } else {
                *(float2*)(g_v + base) = v;
            }
        }
    }
}

// ---------------------------------------------------------------------------
// Kernel 2: V transpose + bf16 split: [BH][S][HD] fp32 -> [BH][HD][S] hi/lo.
// ---------------------------------------------------------------------------
__global__ void __launch_bounds__(256) vt_split_kernel()
{
    __shared__ float t[32][33];
    const int tx = threadIdx.x & 31, ty = threadIdx.x >> 5;
    const int s0 = blockIdx.x * 32, d0 = blockIdx.y * 32, bh = blockIdx.z;
    const float* V = g_v + (size_t)bh * S_ * HD_;
#pragma unroll
    for (int i = 0; i < 4; i++)
        t[ty + i * 8][tx] = V[(size_t)(s0 + ty + i * 8) * HD_ + d0 + tx];
    __syncthreads();
    bf16* vh = g_vthi + ((size_t)bh * HD_) * S_;
    bf16* vl = g_vtlo + ((size_t)bh * HD_) * S_;
#pragma unroll
    for (int i = 0; i < 4; i++) {
        const int d = d0 + ty + i * 8;
        bf16 h, l;
        split1(t[tx][ty + i * 8], h, l);
        vh[(size_t)d * S_ + s0 + tx] = h;
        vl[(size_t)d * S_ + s0 + tx] = l;
    }
}

// ---------------------------------------------------------------------------
// Kernel 3: scores via mma.sync. grid (16 n, 16 m, 64 bh). 128x128, K=64.
// D = Q K^T (split 3-term), then exp(s-12) -> probs + partial row sums.
// smem: [Qhi 16K | Qlo 16K | Khi 16K | Klo 16K]; epilogue overlays f32 stage
// 128x132 (67584B); ps[2][128] at 67584.
// ---------------------------------------------------------------------------
__global__ void __launch_bounds__(256) scores_mma_kernel(float* __restrict__ probs)
{
    extern __shared__ char smem[];
    const int tid = threadIdx.x, lane = tid & 31, wid = tid >> 5;
    const int wm = wid & 3, wn = wid >> 2;          // 4 x 2 warp grid
    const int n0 = blockIdx.x * 128, m0 = blockIdx.y * 128, bh = blockIdx.z;

    // fill 4 tiles (rows are contiguous 128B in global)
    {
        const char* srcs[4] = {
            (const char*)g_qhi + ((size_t)(bh * S_ + m0)) * 128,
            (const char*)g_qlo + ((size_t)(bh * S_ + m0)) * 128,
            (const char*)g_khi + ((size_t)(bh * S_ + n0)) * 128,
            (const char*)g_klo + ((size_t)(bh * S_ + n0)) * 128 };
        for (int u = tid; u < 4096; u += 256) {
            const int t = u >> 10, w = u & 1023;
            const unsigned off = (unsigned)w * 16;
            *(uint4*)(smem + t * 16384 + sw128(off)) = *(const uint4*)(srcs[t] + off);
        }
    }
    __syncthreads();

    const unsigned qhi = smem_u32(smem);
    const unsigned qlo = qhi + 16384, khi = qhi + 32768, klo = qhi + 49152;

    float acc[2][8][4];
#pragma unroll
    for (int mt = 0; mt < 2; mt++)
#pragma unroll
        for (int nt = 0; nt < 8; nt++)
#pragma unroll
            for (int e = 0; e < 4; e++) acc[mt][nt][e] = 0.f;

    const int arow = wm * 32 + (lane & 15);
    const int akb  = (lane >> 4) * 16;
    const int brow = wn * 64 + (lane & 7) + ((lane >> 4) << 3);
    const int bkb  = ((lane >> 3) & 1) * 16;

#pragma unroll
    for (int kc = 0; kc < 4; kc++) {
        const int kb = kc * 32;
        unsigned ah[2][4], al[2][4], bt[4][4];
        ldsm4(ah[0], swadr(qhi, arow,      kb + akb));
        ldsm4(ah[1], swadr(qhi, arow + 16, kb + akb));
        ldsm4(al[0], swadr(qlo, arow,      kb + akb));
        ldsm4(al[1], swadr(qlo, arow + 16, kb + akb));
#pragma unroll
        for (int t = 0; t < 4; t++) ldsm4(bt[t], swadr(khi, brow + t * 16, kb + bkb));
#pragma unroll
        for (int mt = 0; mt < 2; mt++)
#pragma unroll
            for (int nt = 0; nt < 8; nt++)
                mma16816(acc[mt][nt], ah[mt], &bt[nt >> 1][(nt & 1) * 2]);
#pragma unroll
        for (int mt = 0; mt < 2; mt++)
#pragma unroll
            for (int nt = 0; nt < 8; nt++)
                mma16816(acc[mt][nt], al[mt], &bt[nt >> 1][(nt & 1) * 2]);
#pragma unroll
        for (int t = 0; t < 4; t++) ldsm4(bt[t], swadr(klo, brow + t * 16, kb + bkb));
#pragma unroll
        for (int mt = 0; mt < 2; mt++)
#pragma unroll
            for (int nt = 0; nt < 8; nt++)
                mma16816(acc[mt][nt], ah[mt], &bt[nt >> 1][(nt & 1) * 2]);
    }
    __syncthreads();   // done reading tiles; stage overlays them

    float* stage = (float*)smem;              // [128][132]
    float* ps    = (float*)(smem + 67584);    // [2][128]

    float rs[2][2] = {{0.f, 0.f}, {0.f, 0.f}};
#pragma unroll
    for (int mt = 0; mt < 2; mt++) {
        const int r0 = wm * 32 + mt * 16 + (lane >> 2);
#pragma unroll
        for (int nt = 0; nt < 8; nt++) {
            float* a = acc[mt][nt];
            a[0] = __expf(a[0] - 12.f); a[1] = __expf(a[1] - 12.f);
            a[2] = __expf(a[2] - 12.f); a[3] = __expf(a[3] - 12.f);
            rs[mt][0] += a[0] + a[1];
            rs[mt][1] += a[2] + a[3];
            const int cc = wn * 64 + nt * 8 + (lane & 3) * 2;
            *(float2*)&stage[r0 * 132 + cc]       = make_float2(a[0], a[1]);
            *(float2*)&stage[(r0 + 8) * 132 + cc] = make_float2(a[2], a[3]);
        }
#pragma unroll
        for (int h = 0; h < 2; h++) {
            rs[mt][h] += __shfl_xor_sync(0xffffffffu, rs[mt][h], 1);
            rs[mt][h] += __shfl_xor_sync(0xffffffffu, rs[mt][h], 2);
        }
        if ((lane & 3) == 0) {
            const int q = lane >> 2;
            ps[wn * 128 + wm * 32 + mt * 16 + q]     = rs[mt][0];
            ps[wn * 128 + wm * 32 + mt * 16 + q + 8] = rs[mt][1];
        }
    }
    __syncthreads();

    float* P = probs + (size_t)bh * S_ * S_;
    for (int u = tid; u < 4096; u += 256) {
        const int r = u >> 5, c4 = (u & 31) * 4;
        float4 o;
        o.x = stage[r * 132 + c4 + 0]; o.y = stage[r * 132 + c4 + 1];
        o.z = stage[r * 132 + c4 + 2]; o.w = stage[r * 132 + c4 + 3];
        *(float4*)(P + (size_t)(m0 + r) * S_ + n0 + c4) = o;
    }
    if (tid < 128)
        g_psum[((size_t)bh * S_ + m0 + tid) * 16 + blockIdx.x] = ps[tid] + ps[128 + tid];
}

// ---------------------------------------------------------------------------
// Kernel 4: 1/rowsum.
// ---------------------------------------------------------------------------
__global__ void __launch_bounds__(256) rsum_kernel()
{
    const int r = blockIdx.x * 256 + threadIdx.x;
    const float4* p = (const float4*)(g_psum + (size_t)r * 16);
    float4 a = p[0], b = p[1], c = p[2], d = p[3];
    float s = ((a.x + a.y) + (a.z + a.w)) + ((b.x + b.y) + (b.z + b.w))
            + ((c.x + c.y) + (c.z + c.w)) + ((d.x + d.y) + (d.z + d.w));
    g_inv[r] = 1.0f / s;
}

// ---------------------------------------------------------------------------
// Kernel 5: ctx via mma.sync. grid (16 m, 64 bh). M=128, N=64, K=2048 in 32
// chunks of 64. Fill normalizes P (writes probs back) + bf16 split; V from
// pre-split transposed tiles. Double-buffered with register prefetch.
// smem: s_inv[128] @0 ; buffers @512 + b*49152 = {Phi 16K|Plo 16K|Vhi 8K|Vlo 8K}.
// ---------------------------------------------------------------------------
__global__ void __launch_bounds__(256) ctx_mma_kernel(float* __restrict__ probs)
{
    extern __shared__ char smem[];
    const int tid = threadIdx.x, lane = tid & 31, wid = tid >> 5;
    const int m0 = blockIdx.x * 128, bh = blockIdx.y;

    float* s_inv = (float*)smem;
    if (tid < 128) s_inv[tid] = g_inv[bh * S_ + m0 + tid];

    float* P = probs + (size_t)bh * S_ * S_;
    const char* VTh = (const char*)g_vthi + ((size_t)bh * HD_) * S_ * 2;
    const char* VTl = (const char*)g_vtlo + ((size_t)bh * HD_) * S_ * 2;

    // per-thread fill coordinates
    const int pr = tid >> 4, pq4 = (tid & 15) * 4;   // P: rows via +16/iter? no: u = tid + t*256
    (void)pr; (void)pq4;

    float4 pv[8];
    uint4 vh[2], vl[2];
    int kc_pf = 0;

#define CTX_PREFETCH(c) do {                                                \
    const int kc = (c) * 64; kc_pf = kc;                                    \
    _Pragma("unroll")                                                       \
    for (int t = 0; t < 8; t++) {                                           \
        const int u = tid + t * 256;                                        \
        const int r = u >> 4, q4 = (u & 15) * 4;                            \
        pv[t] = *(const float4*)(P + (size_t)(m0 + r) * S_ + kc + q4);      \
    }                                                                       \
    _Pragma("unroll")                                                       \
    for (int t = 0; t < 2; t++) {                                           \
        const int u = tid + t * 256;                                        \
        const int r = u >> 3, cb = (u & 7) * 16;                            \
        vh[t] = *(const uint4*)(VTh + ((size_t)r * S_ + kc) * 2 + cb);      \
        vl[t] = *(const uint4*)(VTl + ((size_t)r * S_ + kc) * 2 + cb);      \
    }                                                                       \
} while (0)

#define CTX_STORE(BUF) do {                                                 \
    char* Phi = smem + 512 + (BUF) * 49152;                                 \
    char* Plo = Phi + 16384;                                                \
    char* Vhi = Phi + 32768;                                                \
    char* Vlo = Phi + 40960;                                                \
    _Pragma("unroll")                                                       \
    for (int t = 0; t < 8; t++) {                                           \
        const int u = tid + t * 256;                                        \
        const int r = u >> 4, q4 = (u & 15) * 4;                            \
        float4 v = pv[t];                                                   \
        const float iv = s_inv[r];                                          \
        v.x *= iv; v.y *= iv; v.z *= iv; v.w *= iv;                         \
        *(float4*)(P + (size_t)(m0 + r) * S_ + kc_pf + q4) = v;             \
        bf16 h0,l0,h1,l1,h2,l2,h3,l3;                                       \
        split1(v.x,h0,l0); split1(v.y,h1,l1);                               \
        split1(v.z,h2,l2); split1(v.w,h3,l3);                               \
        const unsigned off = sw128((unsigned)(r * 128 + q4 * 2));           \
        __nv_bfloat162 hh0; hh0.x=h0; hh0.y=h1;                             \
        __nv_bfloat162 hh1; hh1.x=h2; hh1.y=h3;                             \
        __nv_bfloat162 ll0; ll0.x=l0; ll0.y=l1;                             \
        __nv_bfloat162 ll1; ll1.x=l2; ll1.y=l3;                             \
        *(__nv_bfloat162*)(Phi + off)     = hh0;                            \
        *(__nv_bfloat162*)(Phi + off + 4) = hh1;                            \
        *(__nv_bfloat162*)(Plo + off)     = ll0;                            \
        *(__nv_bfloat162*)(Plo + off + 4) = ll1;                            \
    }                                                                       \
    _Pragma("unroll")                                                       \
    for (int t = 0; t < 2; t++) {                                           \
        const int u = tid + t * 256;                                        \
        const int r = u >> 3, cb = (u & 7) * 16;                            \
        const unsigned off = sw128((unsigned)(r * 128 + cb));               \
        *(uint4*)(Vhi + off) = vh[t];                                       \
        *(uint4*)(Vlo + off) = vl[t];                                       \
    }                                                                       \
} while (0)

    float acc[8][4];
#pragma unroll
    for (int nt = 0; nt < 8; nt++)
#pragma unroll
        for (int e = 0; e < 4; e++) acc[nt][e] = 0.f;

    const int arow = wid * 16 + (lane & 15);
    const int akb  = (lane >> 4) * 16;
    const int brow = (lane & 7) + ((lane >> 4) << 3);
    const int bkb  = ((lane >> 3) & 1) * 16;
    const unsigned sbase = smem_u32(smem);

    __syncthreads();           // s_inv visible
    CTX_PREFETCH(0);
    CTX_STORE(0);
    __syncthreads();

    for (int c = 0; c < 32; c++) {
        const int b = c & 1;
        if (c < 31) CTX_PREFETCH(c + 1);

        const unsigned Phi = sbase + 512 + b * 49152;
        const unsigned Plo = Phi + 16384, Vhi = Phi + 32768, Vlo = Phi + 40960;
#pragma unroll
        for (int k16 = 0; k16 < 4; k16++) {
            const int kb = k16 * 32;
            unsigned ah[4], al[4], bt[4][4];
            ldsm4(ah, swadr(Phi, arow, kb + akb));
            ldsm4(al, swadr(Plo, arow, kb + akb));
#pragma unroll
            for (int t = 0; t < 4; t++) ldsm4(bt[t], swadr(Vhi, brow + t * 16, kb + bkb));
#pragma unroll
            for (int nt = 0; nt < 8; nt++) mma16816(acc[nt], ah, &bt[nt >> 1][(nt & 1) * 2]);
#pragma unroll
            for (int nt = 0; nt < 8; nt++) mma16816(acc[nt], al, &bt[nt >> 1][(nt & 1) * 2]);
#pragma unroll
            for (int t = 0; t < 4; t++) ldsm4(bt[t], swadr(Vlo, brow + t * 16, kb + bkb));
#pragma unroll
            for (int nt = 0; nt < 8; nt++) mma16816(acc[nt], ah, &bt[nt >> 1][(nt & 1) * 2]);
        }
        if (c < 31) CTX_STORE(b ^ 1);
        __syncthreads();
    }
#undef CTX_PREFETCH
#undef CTX_STORE

    // epilogue: stage fp32 [128][68] then coalesced store to g_ctx
    float* stage = (float*)(smem + 512);
    {
        const int r0 = wid * 16 + (lane >> 2);
#pragma unroll
        for (int nt = 0; nt < 8; nt++) {
            const int cc = nt * 8 + (lane & 3) * 2;
            *(float2*)&stage[r0 * 68 + cc]       = make_float2(acc[nt][0], acc[nt][1]);
            *(float2*)&stage[(r0 + 8) * 68 + cc] = make_float2(acc[nt][2], acc[nt][3]);
        }
    }
    __syncthreads();

    const int bb = bh >> 4, h = bh & 15;
    for (int u = tid; u < 2048; u += 256) {
        const int r = u >> 4, c4 = (u & 15) * 4;
        float4 o;
        o.x = stage[r * 68 + c4 + 0]; o.y = stage[r * 68 + c4 + 1];
        o.z = stage[r * 68 + c4 + 2]; o.w = stage[r * 68 + c4 + 3];
        *(float4*)(g_ctx + ((size_t)(bb * S_ + m0 + r)) * H_ + h * HD_ + c4) = o;
    }
}

// ---------------------------------------------------------------------------
// Kernel 6: out = ctx @ Wo.T + bo + hidden (FFMA2).
// ---------------------------------------------------------------------------
__global__ void __launch_bounds__(256, 2) outproj_kernel(
    const float* __restrict__ W,
    const float* __restrict__ bias,
    const float* __restrict__ hid,
    float* __restrict__ out)
{
    constexpr int LDA = 132;
    __shared__ __align__(16) float As[2][16 * LDA];
    __shared__ __align__(16) float Bs[2][16 * LDA];

    const int tid = threadIdx.x;
    const int n0 = blockIdx.x * 128, m0 = blockIdx.y * 128;
    const int tx = tid & 15, ty = tid >> 4;
    const int lrow = tid >> 2, c4 = (tid & 3) * 4;

    const float* xA0 = g_ctx + (size_t)(m0 + lrow) * H_ + c4;
    const float* xA1 = xA0 + (size_t)64 * H_;
    const float* xB0 = W + (size_t)(n0 + lrow) * H_ + c4;
    const float* xB1 = xB0 + (size_t)64 * H_;

    u64 acc[8][4];
#pragma unroll
    for (int i = 0; i < 8; i++)
#pragma unroll
        for (int p = 0; p < 4; p++) acc[i][p] = 0ULL;

    float4 a0s = *(const float4*)(xA0), a1s = *(const float4*)(xA1);
    float4 b0s = *(const float4*)(xB0), b1s = *(const float4*)(xB1);

#define OP_STORE(BUF) do {                                                 \
    float* as = &As[BUF][0]; float* bs = &Bs[BUF][0];                      \
    as[(c4+0)*LDA + lrow]      = a0s.x; as[(c4+1)*LDA + lrow]      = a0s.y;\
    as[(c4+2)*LDA + lrow]      = a0s.z; as[(c4+3)*LDA + lrow]      = a0s.w;\
    as[(c4+0)*LDA + lrow + 64] = a1s.x; as[(c4+1)*LDA + lrow + 64] = a1s.y;\
    as[(c4+2)*LDA + lrow + 64] = a1s.z; as[(c4+3)*LDA + lrow + 64] = a1s.w;\
    bs[(c4+0)*LDA + lrow]      = b0s.x; bs[(c4+1)*LDA + lrow]      = b0s.y;\
    bs[(c4+2)*LDA + lrow]      = b0s.z; bs[(c4+3)*LDA + lrow]      = b0s.w;\
    bs[(c4+0)*LDA + lrow + 64] = b1s.x; bs[(c4+1)*LDA + lrow + 64] = b1s.y;\
    bs[(c4+2)*LDA + lrow + 64] = b1s.z; bs[(c4+3)*LDA + lrow + 64] = b1s.w;\
} while (0)

    OP_STORE(0);
    __syncthreads();

    for (int it = 0; it < 64; it++) {
        const int buf = it & 1;
        if (it < 63) {
            const int k0 = (it + 1) * 16;
            a0s = *(const float4*)(xA0 + k0); a1s = *(const float4*)(xA1 + k0);
            b0s = *(const float4*)(xB0 + k0); b1s = *(const float4*)(xB1 + k0);
        }
#pragma unroll
        for (int kk = 0; kk < 16; kk++) {
            const float* as = &As[buf][kk * LDA];
            const float* bs = &Bs[buf][kk * LDA];
            float4 a0 = *(const float4*)(as + ty * 8);
            float4 a1 = *(const float4*)(as + ty * 8 + 4);
            u64 ad[8];
            ad[0] = pk2(a0.x, a0.x); ad[1] = pk2(a0.y, a0.y);
            ad[2] = pk2(a0.z, a0.z); ad[3] = pk2(a0.w, a0.w);
            ad[4] = pk2(a1.x, a1.x); ad[5] = pk2(a1.y, a1.y);
            ad[6] = pk2(a1.z, a1.z); ad[7] = pk2(a1.w, a1.w);
            u64 b0 = *(const u64*)(bs + 0 * 32 + tx * 2);
            u64 b1 = *(const u64*)(bs + 1 * 32 + tx * 2);
            u64 b2 = *(const u64*)(bs + 2 * 32 + tx * 2);
            u64 b3 = *(const u64*)(bs + 3 * 32 + tx * 2);
#pragma unroll
            for (int i = 0; i < 8; i++) {
                fma2(acc[i][0], ad[i], b0); fma2(acc[i][1], ad[i], b1);
                fma2(acc[i][2], ad[i], b2); fma2(acc[i][3], ad[i], b3);
            }
        }
        if (it < 63) OP_STORE(buf ^ 1);
        __syncthreads();
    }
#undef OP_STORE

#pragma unroll
    for (int i = 0; i < 8; i++) {
        const int m = m0 + ty * 8 + i;
#pragma unroll
        for (int p = 0; p < 4; p++) {
            float2 v = up2(acc[i][p]);
            const int n = n0 + p * 32 + tx * 2;
            float2 bb = *(const float2*)(bias + n);
            float2 hh = *(const float2*)(hid + (size_t)m * H_ + n);
            v.x += bb.x + hh.x;
            v.y += bb.y + hh.y;
            *(float2*)(out + (size_t)m * H_ + n) = v;
        }
    }
}

// ---------------------------------------------------------------------------
extern "C" void kernel_launch(void* const* d_in, const int* in_sizes, int n_in,
                              void* d_out, int out_size)
{
    (void)in_sizes; (void)n_in;

    const float* hs = (const float*)d_in[0];
    const float* Wq = (const float*)d_in[1];
    const float* bq = (const float*)d_in[2];
    const float* Wk = (const float*)d_in[3];
    const float* bk = (const float*)d_in[4];
    const float* Wv = (const float*)d_in[5];
    const float* bv = (const float*)d_in[6];
    const float* Wo = (const float*)d_in[7];
    const float* bo = (const float*)d_in[8];
    float* out = (float*)d_out;

    float* probs;
    if ((long long)out_size >= OUT_ELEMS + PROBS_ELEMS) {
        probs = out + OUT_ELEMS;
    } else {
        void* p = nullptr;
        cudaGetSymbolAddress(&p, g_probs_fallback);
        probs = (float*)p;
    }

    cudaFuncSetAttribute(scores_mma_kernel, cudaFuncAttributeMaxDynamicSharedMemorySize, SC_SMEM);
    cudaFuncSetAttribute(ctx_mma_kernel,    cudaFuncAttributeMaxDynamicSharedMemorySize, CTX_SMEM);

    proj_qkv_kernel<<<dim3(H_ / 128, M_ / 128, 3), 256>>>(hs, Wq, bq, Wk, bk, Wv, bv);
    vt_split_kernel<<<dim3(S_ / 32, HD_ / 32, BH_), 256>>>();
    scores_mma_kernel<<<dim3(S_ / 128, S_ / 128, BH_), 256, SC_SMEM>>>(probs);
    rsum_kernel<<<(BH_ * S_) / 256, 256>>>();
    ctx_mma_kernel<<<dim3(S_ / 128, BH_), 256, CTX_SMEM>>>(probs);
    outproj_kernel<<<dim3(H_ / 128, M_ / 128), 256>>>(Wo, bo, hs, out);
}

// round 16
// speedup vs baseline: 1.7595x; 1.4036x over previous
#include <cuda_runtime.h>
#include <cuda_bf16.h>

// ---------------------------------------------------------------------------
// AttentionBlock. pproc == plain linear in fwd. B=4,S=2048,H=1024,NH=16,HD=64.
// Output = [out (B,S,H)] ++ [probs (B,NH,S,S)], fp32.
// R16: ALL GEMMs via mma.sync bf16 2-term split (hi*hi + hi*lo + lo*hi).
//      proj/outproj use cp.async double-buffered fills, K=1024 in 16 chunks.
// ---------------------------------------------------------------------------

namespace {
constexpr int B_  = 4;
constexpr int S_  = 2048;
constexpr int H_  = 1024;
constexpr int NH_ = 16;
constexpr int HD_ = 64;
constexpr int M_  = B_ * S_;
constexpr int BH_ = B_ * NH_;
constexpr long long OUT_ELEMS   = (long long)M_ * H_;
constexpr long long PROBS_ELEMS = (long long)BH_ * S_ * S_;

constexpr int SC_SMEM   = 68608;            // scores: tiles 64K / stage 67584 + ps 1K
constexpr int CTX_SMEM  = 512 + 2 * 49152;  // ctx: s_inv + 2 x (Phi|Plo|Vhi|Vlo)
constexpr int GEMM_SMEM = 2 * 65536;        // proj/outproj: 2 x (Ahi|Alo|Bhi|Blo)
}

typedef unsigned long long u64;
typedef __nv_bfloat16 bf16;

// ---------------- scratch ---------------------------------------------------
__device__ bf16  g_xhi[M_ * H_],  g_xlo[M_ * H_];      // X split [8192][1024]
__device__ bf16  g_whi[4 * H_ * H_], g_wlo[4 * H_ * H_]; // Wq,Wk,Wv,Wo split
__device__ bf16  g_qhi[M_ * H_], g_qlo[M_ * H_];       // [BH][S][HD]
__device__ bf16  g_khi[M_ * H_], g_klo[M_ * H_];       // [BH][S][HD]
__device__ float g_v[M_ * H_];                         // [BH][S][HD]
__device__ bf16  g_vthi[M_ * H_], g_vtlo[M_ * H_];     // [BH][HD][S]
__device__ bf16  g_chi[M_ * H_], g_clo[M_ * H_];       // ctx split [B,S,H]
__device__ float g_psum[(long long)BH_ * S_ * 16];
__device__ float g_inv[BH_ * S_];
__device__ float g_probs_fallback[268435456];

// ---------------- helpers ----------------------------------------------------
__device__ __forceinline__ unsigned smem_u32(const void* p) {
    unsigned a;
    asm("{ .reg .u64 t; cvta.to.shared.u64 t, %1; cvt.u32.u64 %0, t; }" : "=r"(a) : "l"(p));
    return a;
}
__device__ __forceinline__ unsigned sw128(unsigned off) { return off ^ ((off >> 3) & 0x70); }
__device__ __forceinline__ unsigned swadr(unsigned base, int row, int kbyte) {
    unsigned off = (unsigned)(row * 128 + kbyte);
    return base + (off ^ ((off >> 3) & 0x70));
}
__device__ __forceinline__ void ldsm4(unsigned r[4], unsigned addr) {
    asm volatile("ldmatrix.sync.aligned.m8n8.x4.shared.b16 {%0,%1,%2,%3}, [%4];"
        : "=r"(r[0]), "=r"(r[1]), "=r"(r[2]), "=r"(r[3]) : "r"(addr));
}
__device__ __forceinline__ void mma16816(float d[4], const unsigned a[4], const unsigned b[2]) {
    asm volatile(
        "mma.sync.aligned.m16n8k16.row.col.f32.bf16.bf16.f32 "
        "{%0,%1,%2,%3}, {%4,%5,%6,%7}, {%8,%9}, {%0,%1,%2,%3};"
        : "+f"(d[0]), "+f"(d[1]), "+f"(d[2]), "+f"(d[3])
        : "r"(a[0]), "r"(a[1]), "r"(a[2]), "r"(a[3]), "r"(b[0]), "r"(b[1]));
}
__device__ __forceinline__ void split1(float x, bf16& h, bf16& l) {
    h = __float2bfloat16(x);
    l = __float2bfloat16(x - __bfloat162float(h));
}
__device__ __forceinline__ void cpa16(unsigned dst, const void* src) {
    asm volatile("cp.async.cg.shared.global [%0], [%1], 16;" :: "r"(dst), "l"(src));
}
__device__ __forceinline__ void cpa_commit() {
    asm volatile("cp.async.commit_group;" ::: "memory");
}

// Fill one double-buffer slot: 4 tiles (Ahi|Alo|Bhi|Blo), each 128 rows x 128B,
// sources have 2048B row stride (K=1024 bf16), chunk byte offset kb2.
__device__ __forceinline__ void fill_tiles_cpa(unsigned sbase, int buf,
    const char* s0, const char* s1, const char* s2, const char* s3,
    int kb2, int tid)
{
    const char* srcs[4] = {s0, s1, s2, s3};
#pragma unroll
    for (int t = 0; t < 16; t++) {
        const int u = tid + t * 256;
        const int tt = u >> 10, w = u & 1023;
        const int r = w >> 3, sg = (w & 7) * 16;
        cpa16(sbase + buf * 65536 + tt * 16384 + sw128((unsigned)(r * 128 + sg)),
              srcs[tt] + (size_t)r * 2048 + kb2 + sg);
    }
    cpa_commit();
}

// ---------------------------------------------------------------------------
// Kernel 0: fp32 -> (bf16 hi, lo) split.
// ---------------------------------------------------------------------------
__global__ void __launch_bounds__(256) cvt_kernel(const float* __restrict__ src,
    bf16* __restrict__ dh, bf16* __restrict__ dl)
{
    const int i = blockIdx.x * 256 + threadIdx.x;
    float4 v = ((const float4*)src)[i];
    union { bf16 b[4]; uint2 u; } Hh, Ll;
    split1(v.x, Hh.b[0], Ll.b[0]);
    split1(v.y, Hh.b[1], Ll.b[1]);
    split1(v.z, Hh.b[2], Ll.b[2]);
    split1(v.w, Hh.b[3], Ll.b[3]);
    ((uint2*)dh)[i] = Hh.u;
    ((uint2*)dl)[i] = Ll.u;
}

// ---------------------------------------------------------------------------
// Kernel 1: QKV projection (mma.sync). grid (8, 64, 3). 128x128, K=1024.
// sel 0/1 -> bf16 split q/k [BH][S][HD]; sel 2 -> fp32 v.
// ---------------------------------------------------------------------------
__global__ void __launch_bounds__(256) proj_mma_kernel(
    const float* __restrict__ bq, const float* __restrict__ bk,
    const float* __restrict__ bv)
{
    extern __shared__ char smem[];
    const int tid = threadIdx.x, lane = tid & 31, wid = tid >> 5;
    const int wm = wid & 3, wn = wid >> 2;
    const int sel = blockIdx.z;
    const int n0 = blockIdx.x * 128, m0 = blockIdx.y * 128;
    const unsigned sb = smem_u32(smem);

    const char* Ah = (const char*)g_xhi + (size_t)m0 * 2048;
    const char* Al = (const char*)g_xlo + (size_t)m0 * 2048;
    const char* Bh = (const char*)(g_whi + (size_t)sel * H_ * H_) + (size_t)n0 * 2048;
    const char* Bl = (const char*)(g_wlo + (size_t)sel * H_ * H_) + (size_t)n0 * 2048;

    float acc[2][8][4];
#pragma unroll
    for (int mt = 0; mt < 2; mt++)
#pragma unroll
        for (int nt = 0; nt < 8; nt++)
#pragma unroll
            for (int e = 0; e < 4; e++) acc[mt][nt][e] = 0.f;

    const int arow = wm * 32 + (lane & 15);
    const int akb  = (lane >> 4) * 16;
    const int brow = wn * 64 + (lane & 7) + ((lane >> 4) << 3);
    const int bkb  = ((lane >> 3) & 1) * 16;

    fill_tiles_cpa(sb, 0, Ah, Al, Bh, Bl, 0, tid);
    fill_tiles_cpa(sb, 1, Ah, Al, Bh, Bl, 128, tid);

    for (int c = 0; c < 16; c++) {
        if (c < 15) asm volatile("cp.async.wait_group 1;" ::: "memory");
        else        asm volatile("cp.async.wait_group 0;" ::: "memory");
        __syncthreads();

        const int b = c & 1;
        const unsigned Thi = sb + b * 65536;
        const unsigned Tlo = Thi + 16384, Tbh = Thi + 32768, Tbl = Thi + 49152;
#pragma unroll
        for (int k16 = 0; k16 < 4; k16++) {
            const int kb = k16 * 32;
            unsigned ah[2][4], al[2][4], bt[4][4];
            ldsm4(ah[0], swadr(Thi, arow,      kb + akb));
            ldsm4(ah[1], swadr(Thi, arow + 16, kb + akb));
            ldsm4(al[0], swadr(Tlo, arow,      kb + akb));
            ldsm4(al[1], swadr(Tlo, arow + 16, kb + akb));
#pragma unroll
            for (int t = 0; t < 4; t++) ldsm4(bt[t], swadr(Tbh, brow + t * 16, kb + bkb));
#pragma unroll
            for (int mt = 0; mt < 2; mt++)
#pragma unroll
                for (int nt = 0; nt < 8; nt++)
                    mma16816(acc[mt][nt], ah[mt], &bt[nt >> 1][(nt & 1) * 2]);
#pragma unroll
            for (int mt = 0; mt < 2; mt++)
#pragma unroll
                for (int nt = 0; nt < 8; nt++)
                    mma16816(acc[mt][nt], al[mt], &bt[nt >> 1][(nt & 1) * 2]);
#pragma unroll
            for (int t = 0; t < 4; t++) ldsm4(bt[t], swadr(Tbl, brow + t * 16, kb + bkb));
#pragma unroll
            for (int mt = 0; mt < 2; mt++)
#pragma unroll
                for (int nt = 0; nt < 8; nt++)
                    mma16816(acc[mt][nt], ah[mt], &bt[nt >> 1][(nt & 1) * 2]);
        }
        __syncthreads();
        if (c + 2 < 16)
            fill_tiles_cpa(sb, b, Ah, Al, Bh, Bl, (c + 2) * 128, tid);
    }

    const float* bias = (sel == 0) ? bq : (sel == 1) ? bk : bv;
    bf16* dh = (sel == 0) ? g_qhi : g_khi;
    bf16* dl = (sel == 0) ? g_qlo : g_klo;

#pragma unroll
    for (int mt = 0; mt < 2; mt++) {
        const int r0 = wm * 32 + mt * 16 + (lane >> 2);
#pragma unroll
        for (int nt = 0; nt < 8; nt++) {
            const int cc = wn * 64 + nt * 8 + (lane & 3) * 2;
            const int n = n0 + cc;
            const float b0 = bias[n], b1 = bias[n + 1];
            const int h = n >> 6, d = n & 63;
#pragma unroll
            for (int rh = 0; rh < 2; rh++) {
                const int m = m0 + r0 + rh * 8;
                const int bb = m >> 11, s = m & (S_ - 1);
                const float v0 = acc[mt][nt][rh * 2 + 0] + b0;
                const float v1 = acc[mt][nt][rh * 2 + 1] + b1;
                const size_t base = ((size_t)((bb << 4) + h) * S_ + s) * HD_ + d;
                if (sel < 2) {
                    bf16 h0, l0, h1, l1;
                    split1(v0, h0, l0); split1(v1, h1, l1);
                    __nv_bfloat162 hh; hh.x = h0; hh.y = h1;
                    __nv_bfloat162 ll; ll.x = l0; ll.y = l1;
                    *(__nv_bfloat162*)(dh + base) = hh;
                    *(__nv_bfloat162*)(dl + base) = ll;
                } else {
                    *(float2*)(g_v + base) = make_float2(v0, v1);
                }
            }
        }
    }
}

// ---------------------------------------------------------------------------
// Kernel 2: V transpose + bf16 split: [BH][S][HD] fp32 -> [BH][HD][S] hi/lo.
// ---------------------------------------------------------------------------
__global__ void __launch_bounds__(256) vt_split_kernel()
{
    __shared__ float t[32][33];
    const int tx = threadIdx.x & 31, ty = threadIdx.x >> 5;
    const int s0 = blockIdx.x * 32, d0 = blockIdx.y * 32, bh = blockIdx.z;
    const float* V = g_v + (size_t)bh * S_ * HD_;
#pragma unroll
    for (int i = 0; i < 4; i++)
        t[ty + i * 8][tx] = V[(size_t)(s0 + ty + i * 8) * HD_ + d0 + tx];
    __syncthreads();
    bf16* vh = g_vthi + ((size_t)bh * HD_) * S_;
    bf16* vl = g_vtlo + ((size_t)bh * HD_) * S_;
#pragma unroll
    for (int i = 0; i < 4; i++) {
        const int d = d0 + ty + i * 8;
        bf16 h, l;
        split1(t[tx][ty + i * 8], h, l);
        vh[(size_t)d * S_ + s0 + tx] = h;
        vl[(size_t)d * S_ + s0 + tx] = l;
    }
}

// ---------------------------------------------------------------------------
// Kernel 3: scores (mma.sync). grid (16 n, 16 m, 64 bh). 128x128, K=64.
// exp(s-12) -> probs + partial row sums.
// ---------------------------------------------------------------------------
__global__ void __launch_bounds__(256) scores_mma_kernel(float* __restrict__ probs)
{
    extern __shared__ char smem[];
    const int tid = threadIdx.x, lane = tid & 31, wid = tid >> 5;
    const int wm = wid & 3, wn = wid >> 2;
    const int n0 = blockIdx.x * 128, m0 = blockIdx.y * 128, bh = blockIdx.z;

    {
        const char* srcs[4] = {
            (const char*)g_qhi + ((size_t)(bh * S_ + m0)) * 128,
            (const char*)g_qlo + ((size_t)(bh * S_ + m0)) * 128,
            (const char*)g_khi + ((size_t)(bh * S_ + n0)) * 128,
            (const char*)g_klo + ((size_t)(bh * S_ + n0)) * 128 };
        for (int u = tid; u < 4096; u += 256) {
            const int t = u >> 10, w = u & 1023;
            const unsigned off = (unsigned)w * 16;
            *(uint4*)(smem + t * 16384 + sw128(off)) = *(const uint4*)(srcs[t] + off);
        }
    }
    __syncthreads();

    const unsigned qhi = smem_u32(smem);
    const unsigned qlo = qhi + 16384, khi = qhi + 32768, klo = qhi + 49152;

    float acc[2][8][4];
#pragma unroll
    for (int mt = 0; mt < 2; mt++)
#pragma unroll
        for (int nt = 0; nt < 8; nt++)
#pragma unroll
            for (int e = 0; e < 4; e++) acc[mt][nt][e] = 0.f;

    const int arow = wm * 32 + (lane & 15);
    const int akb  = (lane >> 4) * 16;
    const int brow = wn * 64 + (lane & 7) + ((lane >> 4) << 3);
    const int bkb  = ((lane >> 3) & 1) * 16;

#pragma unroll
    for (int kc = 0; kc < 4; kc++) {
        const int kb = kc * 32;
        unsigned ah[2][4], al[2][4], bt[4][4];
        ldsm4(ah[0], swadr(qhi, arow,      kb + akb));
        ldsm4(ah[1], swadr(qhi, arow + 16, kb + akb));
        ldsm4(al[0], swadr(qlo, arow,      kb + akb));
        ldsm4(al[1], swadr(qlo, arow + 16, kb + akb));
#pragma unroll
        for (int t = 0; t < 4; t++) ldsm4(bt[t], swadr(khi, brow + t * 16, kb + bkb));
#pragma unroll
        for (int mt = 0; mt < 2; mt++)
#pragma unroll
            for (int nt = 0; nt < 8; nt++)
                mma16816(acc[mt][nt], ah[mt], &bt[nt >> 1][(nt & 1) * 2]);
#pragma unroll
        for (int mt = 0; mt < 2; mt++)
#pragma unroll
            for (int nt = 0; nt < 8; nt++)
                mma16816(acc[mt][nt], al[mt], &bt[nt >> 1][(nt & 1) * 2]);
#pragma unroll
        for (int t = 0; t < 4; t++) ldsm4(bt[t], swadr(klo, brow + t * 16, kb + bkb));
#pragma unroll
        for (int mt = 0; mt < 2; mt++)
#pragma unroll
            for (int nt = 0; nt < 8; nt++)
                mma16816(acc[mt][nt], ah[mt], &bt[nt >> 1][(nt & 1) * 2]);
    }
    __syncthreads();

    float* stage = (float*)smem;              // [128][132]
    float* ps    = (float*)(smem + 67584);    // [2][128]

    float rs[2][2] = {{0.f, 0.f}, {0.f, 0.f}};
#pragma unroll
    for (int mt = 0; mt < 2; mt++) {
        const int r0 = wm * 32 + mt * 16 + (lane >> 2);
#pragma unroll
        for (int nt = 0; nt < 8; nt++) {
            float* a = acc[mt][nt];
            a[0] = __expf(a[0] - 12.f); a[1] = __expf(a[1] - 12.f);
            a[2] = __expf(a[2] - 12.f); a[3] = __expf(a[3] - 12.f);
            rs[mt][0] += a[0] + a[1];
            rs[mt][1] += a[2] + a[3];
            const int cc = wn * 64 + nt * 8 + (lane & 3) * 2;
            *(float2*)&stage[r0 * 132 + cc]       = make_float2(a[0], a[1]);
            *(float2*)&stage[(r0 + 8) * 132 + cc] = make_float2(a[2], a[3]);
        }
#pragma unroll
        for (int h = 0; h < 2; h++) {
            rs[mt][h] += __shfl_xor_sync(0xffffffffu, rs[mt][h], 1);
            rs[mt][h] += __shfl_xor_sync(0xffffffffu, rs[mt][h], 2);
        }
        if ((lane & 3) == 0) {
            const int q = lane >> 2;
            ps[wn * 128 + wm * 32 + mt * 16 + q]     = rs[mt][0];
            ps[wn * 128 + wm * 32 + mt * 16 + q + 8] = rs[mt][1];
        }
    }
    __syncthreads();

    float* P = probs + (size_t)bh * S_ * S_;
    for (int u = tid; u < 4096; u += 256) {
        const int r = u >> 5, c4 = (u & 31) * 4;
        float4 o;
        o.x = stage[r * 132 + c4 + 0]; o.y = stage[r * 132 + c4 + 1];
        o.z = stage[r * 132 + c4 + 2]; o.w = stage[r * 132 + c4 + 3];
        *(float4*)(P + (size_t)(m0 + r) * S_ + n0 + c4) = o;
    }
    if (tid < 128)
        g_psum[((size_t)bh * S_ + m0 + tid) * 16 + blockIdx.x] = ps[tid] + ps[128 + tid];
}

// ---------------------------------------------------------------------------
// Kernel 4: 1/rowsum.
// ---------------------------------------------------------------------------
__global__ void __launch_bounds__(256) rsum_kernel()
{
    const int r = blockIdx.x * 256 + threadIdx.x;
    const float4* p = (const float4*)(g_psum + (size_t)r * 16);
    float4 a = p[0], b = p[1], c = p[2], d = p[3];
    float s = ((a.x + a.y) + (a.z + a.w)) + ((b.x + b.y) + (b.z + b.w))
            + ((c.x + c.y) + (c.z + c.w)) + ((d.x + d.y) + (d.z + d.w));
    g_inv[r] = 1.0f / s;
}

// ---------------------------------------------------------------------------
// Kernel 5: ctx (mma.sync). grid (16 m, 64 bh). M=128, N=64, K=2048, 32 chunks.
// Fill normalizes P (writes probs back) + bf16 split; epilogue writes ctx
// as split bf16 [B,S,H] for outproj_mma.
// ---------------------------------------------------------------------------
__global__ void __launch_bounds__(256) ctx_mma_kernel(float* __restrict__ probs)
{
    extern __shared__ char smem[];
    const int tid = threadIdx.x, lane = tid & 31, wid = tid >> 5;
    const int m0 = blockIdx.x * 128, bh = blockIdx.y;

    float* s_inv = (float*)smem;
    if (tid < 128) s_inv[tid] = g_inv[bh * S_ + m0 + tid];

    float* P = probs + (size_t)bh * S_ * S_;
    const char* VTh = (const char*)g_vthi + ((size_t)bh * HD_) * S_ * 2;
    const char* VTl = (const char*)g_vtlo + ((size_t)bh * HD_) * S_ * 2;

    float4 pv[8];
    uint4 vh[2], vl[2];
    int kc_pf = 0;

#define CTX_PREFETCH(c) do {                                                \
    const int kc = (c) * 64; kc_pf = kc;                                    \
    _Pragma("unroll")                                                       \
    for (int t = 0; t < 8; t++) {                                           \
        const int u = tid + t * 256;                                        \
        const int r = u >> 4, q4 = (u & 15) * 4;                            \
        pv[t] = *(const float4*)(P + (size_t)(m0 + r) * S_ + kc + q4);      \
    }                                                                       \
    _Pragma("unroll")                                                       \
    for (int t = 0; t < 2; t++) {                                           \
        const int u = tid + t * 256;                                        \
        const int r = u >> 3, cb = (u & 7) * 16;                            \
        vh[t] = *(const uint4*)(VTh + ((size_t)r * S_ + kc) * 2 + cb);      \
        vl[t] = *(const uint4*)(VTl + ((size_t)r * S_ + kc) * 2 + cb);      \
    }                                                                       \
} while (0)

#define CTX_STORE(BUF) do {                                                 \
    char* Phi = smem + 512 + (BUF) * 49152;                                 \
    char* Plo = Phi + 16384;                                                \
    char* Vhi = Phi + 32768;                                                \
    char* Vlo = Phi + 40960;                                                \
    _Pragma("unroll")                                                       \
    for (int t = 0; t < 8; t++) {                                           \
        const int u = tid + t * 256;                                        \
        const int r = u >> 4, q4 = (u & 15) * 4;                            \
        float4 v = pv[t];                                                   \
        const float iv = s_inv[r];                                          \
        v.x *= iv; v.y *= iv; v.z *= iv; v.w *= iv;                         \
        *(float4*)(P + (size_t)(m0 + r) * S_ + kc_pf + q4) = v;             \
        bf16 h0,l0,h1,l1,h2,l2,h3,l3;                                       \
        split1(v.x,h0,l0); split1(v.y,h1,l1);                               \
        split1(v.z,h2,l2); split1(v.w,h3,l3);                               \
        const unsigned off = sw128((unsigned)(r * 128 + q4 * 2));           \
        __nv_bfloat162 hh0; hh0.x=h0; hh0.y=h1;                             \
        __nv_bfloat162 hh1; hh1.x=h2; hh1.y=h3;                             \
        __nv_bfloat162 ll0; ll0.x=l0; ll0.y=l1;                             \
        __nv_bfloat162 ll1; ll1.x=l2; ll1.y=l3;                             \
        *(__nv_bfloat162*)(Phi + off)     = hh0;                            \
        *(__nv_bfloat162*)(Phi + off + 4) = hh1;                            \
        *(__nv_bfloat162*)(Plo + off)     = ll0;                            \
        *(__nv_bfloat162*)(Plo + off + 4) = ll1;                            \
    }                                                                       \
    _Pragma("unroll")                                                       \
    for (int t = 0; t < 2; t++) {                                           \
        const int u = tid + t * 256;                                        \
        const int r = u >> 3, cb = (u & 7) * 16;                            \
        const unsigned off = sw128((unsigned)(r * 128 + cb));               \
        *(uint4*)(Vhi + off) = vh[t];                                       \
        *(uint4*)(Vlo + off) = vl[t];                                       \
    }                                                                       \
} while (0)

    float acc[8][4];
#pragma unroll
    for (int nt = 0; nt < 8; nt++)
#pragma unroll
        for (int e = 0; e < 4; e++) acc[nt][e] = 0.f;

    const int arow = wid * 16 + (lane & 15);
    const int akb  = (lane >> 4) * 16;
    const int brow = (lane & 7) + ((lane >> 4) << 3);
    const int bkb  = ((lane >> 3) & 1) * 16;
    const unsigned sbase = smem_u32(smem);

    __syncthreads();
    CTX_PREFETCH(0);
    CTX_STORE(0);
    __syncthreads();

    for (int c = 0; c < 32; c++) {
        const int b = c & 1;
        if (c < 31) CTX_PREFETCH(c + 1);

        const unsigned Phi = sbase + 512 + b * 49152;
        const unsigned Plo = Phi + 16384, Vhi = Phi + 32768, Vlo = Phi + 40960;
#pragma unroll
        for (int k16 = 0; k16 < 4; k16++) {
            const int kb = k16 * 32;
            unsigned ah[4], al[4], bt[4][4];
            ldsm4(ah, swadr(Phi, arow, kb + akb));
            ldsm4(al, swadr(Plo, arow, kb + akb));
#pragma unroll
            for (int t = 0; t < 4; t++) ldsm4(bt[t], swadr(Vhi, brow + t * 16, kb + bkb));
#pragma unroll
            for (int nt = 0; nt < 8; nt++) mma16816(acc[nt], ah, &bt[nt >> 1][(nt & 1) * 2]);
#pragma unroll
            for (int nt = 0; nt < 8; nt++) mma16816(acc[nt], al, &bt[nt >> 1][(nt & 1) * 2]);
#pragma unroll
            for (int t = 0; t < 4; t++) ldsm4(bt[t], swadr(Vlo, brow + t * 16, kb + bkb));
#pragma unroll
            for (int nt = 0; nt < 8; nt++) mma16816(acc[nt], ah, &bt[nt >> 1][(nt & 1) * 2]);
        }
        if (c < 31) CTX_STORE(b ^ 1);
        __syncthreads();
    }
#undef CTX_PREFETCH
#undef CTX_STORE

    float* stage = (float*)(smem + 512);      // [128][68]
    {
        const int r0 = wid * 16 + (lane >> 2);
#pragma unroll
        for (int nt = 0; nt < 8; nt++) {
            const int cc = nt * 8 + (lane & 3) * 2;
            *(float2*)&stage[r0 * 68 + cc]       = make_float2(acc[nt][0], acc[nt][1]);
            *(float2*)&stage[(r0 + 8) * 68 + cc] = make_float2(acc[nt][2], acc[nt][3]);
        }
    }
    __syncthreads();

    const int bb = bh >> 4, h = bh & 15;
    for (int u = tid; u < 2048; u += 256) {
        const int r = u >> 4, c4 = (u & 15) * 4;
        float4 o;
        o.x = stage[r * 68 + c4 + 0]; o.y = stage[r * 68 + c4 + 1];
        o.z = stage[r * 68 + c4 + 2]; o.w = stage[r * 68 + c4 + 3];
        union { bf16 b[4]; uint2 u2; } Hh, Ll;
        split1(o.x, Hh.b[0], Ll.b[0]);
        split1(o.y, Hh.b[1], Ll.b[1]);
        split1(o.z, Hh.b[2], Ll.b[2]);
        split1(o.w, Hh.b[3], Ll.b[3]);
        const size_t dst = ((size_t)(bb * S_ + m0 + r)) * H_ + h * HD_ + c4;
        *(uint2*)(g_chi + dst) = Hh.u2;
        *(uint2*)(g_clo + dst) = Ll.u2;
    }
}

// ---------------------------------------------------------------------------
// Kernel 6: out = ctx @ Wo.T + bo + hidden (mma.sync). grid (8, 64).
// ---------------------------------------------------------------------------
__global__ void __launch_bounds__(256) outproj_mma_kernel(
    const float* __restrict__ bias,
    const float* __restrict__ hid,
    float* __restrict__ out)
{
    extern __shared__ char smem[];
    const int tid = threadIdx.x, lane = tid & 31, wid = tid >> 5;
    const int wm = wid & 3, wn = wid >> 2;
    const int n0 = blockIdx.x * 128, m0 = blockIdx.y * 128;
    const unsigned sb = smem_u32(smem);

    const char* Ah = (const char*)g_chi + (size_t)m0 * 2048;
    const char* Al = (const char*)g_clo + (size_t)m0 * 2048;
    const char* Bh = (const char*)(g_whi + (size_t)3 * H_ * H_) + (size_t)n0 * 2048;
    const char* Bl = (const char*)(g_wlo + (size_t)3 * H_ * H_) + (size_t)n0 * 2048;

    float acc[2][8][4];
#pragma unroll
    for (int mt = 0; mt < 2; mt++)
#pragma unroll
        for (int nt = 0; nt < 8; nt++)
#pragma unroll
            for (int e = 0; e < 4; e++) acc[mt][nt][e] = 0.f;

    const int arow = wm * 32 + (lane & 15);
    const int akb  = (lane >> 4) * 16;
    const int brow = wn * 64 + (lane & 7) + ((lane >> 4) << 3);
    const int bkb  = ((lane >> 3) & 1) * 16;

    fill_tiles_cpa(sb, 0, Ah, Al, Bh, Bl, 0, tid);
    fill_tiles_cpa(sb, 1, Ah, Al, Bh, Bl, 128, tid);

    for (int c = 0; c < 16; c++) {
        if (c < 15) asm volatile("cp.async.wait_group 1;" ::: "memory");
        else        asm volatile("cp.async.wait_group 0;" ::: "memory");
        __syncthreads();

        const int b = c & 1;
        const unsigned Thi = sb + b * 65536;
        const unsigned Tlo = Thi + 16384, Tbh = Thi + 32768, Tbl = Thi + 49152;
#pragma unroll
        for (int k16 = 0; k16 < 4; k16++) {
            const int kb = k16 * 32;
            unsigned ah[2][4], al[2][4], bt[4][4];
            ldsm4(ah[0], swadr(Thi, arow,      kb + akb));
            ldsm4(ah[1], swadr(Thi, arow + 16, kb + akb));
            ldsm4(al[0], swadr(Tlo, arow,      kb + akb));
            ldsm4(al[1], swadr(Tlo, arow + 16, kb + akb));
#pragma unroll
            for (int t = 0; t < 4; t++) ldsm4(bt[t], swadr(Tbh, brow + t * 16, kb + bkb));
#pragma unroll
            for (int mt = 0; mt < 2; mt++)
#pragma unroll
                for (int nt = 0; nt < 8; nt++)
                    mma16816(acc[mt][nt], ah[mt], &bt[nt >> 1][(nt & 1) * 2]);
#pragma unroll
            for (int mt = 0; mt < 2; mt++)
#pragma unroll
                for (int nt = 0; nt < 8; nt++)
                    mma16816(acc[mt][nt], al[mt], &bt[nt >> 1][(nt & 1) * 2]);
#pragma unroll
            for (int t = 0; t < 4; t++) ldsm4(bt[t], swadr(Tbl, brow + t * 16, kb + bkb));
#pragma unroll
            for (int mt = 0; mt < 2; mt++)
#pragma unroll
                for (int nt = 0; nt < 8; nt++)
                    mma16816(acc[mt][nt], ah[mt], &bt[nt >> 1][(nt & 1) * 2]);
        }
        __syncthreads();
        if (c + 2 < 16)
            fill_tiles_cpa(sb, b, Ah, Al, Bh, Bl, (c + 2) * 128, tid);
    }

#pragma unroll
    for (int mt = 0; mt < 2; mt++) {
        const int r0 = wm * 32 + mt * 16 + (lane >> 2);
#pragma unroll
        for (int nt = 0; nt < 8; nt++) {
            const int cc = wn * 64 + nt * 8 + (lane & 3) * 2;
            const int n = n0 + cc;
            const float b0 = bias[n], b1 = bias[n + 1];
#pragma unroll
            for (int rh = 0; rh < 2; rh++) {
                const int m = m0 + r0 + rh * 8;
                const float2 hh = *(const float2*)(hid + (size_t)m * H_ + n);
                float2 v;
                v.x = acc[mt][nt][rh * 2 + 0] + b0 + hh.x;
                v.y = acc[mt][nt][rh * 2 + 1] + b1 + hh.y;
                *(float2*)(out + (size_t)m * H_ + n) = v;
            }
        }
    }
}

// ---------------------------------------------------------------------------
extern "C" void kernel_launch(void* const* d_in, const int* in_sizes, int n_in,
                              void* d_out, int out_size)
{
    (void)in_sizes; (void)n_in;

    const float* hs = (const float*)d_in[0];
    const float* Wq = (const float*)d_in[1];
    const float* bq = (const float*)d_in[2];
    const float* Wk = (const float*)d_in[3];
    const float* bk = (const float*)d_in[4];
    const float* Wv = (const float*)d_in[5];
    const float* bv = (const float*)d_in[6];
    const float* Wo = (const float*)d_in[7];
    const float* bo = (const float*)d_in[8];
    float* out = (float*)d_out;

    float* probs;
    if ((long long)out_size >= OUT_ELEMS + PROBS_ELEMS) {
        probs = out + OUT_ELEMS;
    } else {
        void* p = nullptr;
        cudaGetSymbolAddress(&p, g_probs_fallback);
        probs = (float*)p;
    }

    bf16 *xhi, *xlo, *whi, *wlo;
    { void* p; cudaGetSymbolAddress(&p, g_xhi); xhi = (bf16*)p; }
    { void* p; cudaGetSymbolAddress(&p, g_xlo); xlo = (bf16*)p; }
    { void* p; cudaGetSymbolAddress(&p, g_whi); whi = (bf16*)p; }
    { void* p; cudaGetSymbolAddress(&p, g_wlo); wlo = (bf16*)p; }

    cudaFuncSetAttribute(scores_mma_kernel,  cudaFuncAttributeMaxDynamicSharedMemorySize, SC_SMEM);
    cudaFuncSetAttribute(ctx_mma_kernel,     cudaFuncAttributeMaxDynamicSharedMemorySize, CTX_SMEM);
    cudaFuncSetAttribute(proj_mma_kernel,    cudaFuncAttributeMaxDynamicSharedMemorySize, GEMM_SMEM);
    cudaFuncSetAttribute(outproj_mma_kernel, cudaFuncAttributeMaxDynamicSharedMemorySize, GEMM_SMEM);

    // splits
    cvt_kernel<<<(M_ * H_) / 1024, 256>>>(hs, xhi, xlo);
    cvt_kernel<<<(H_ * H_) / 1024, 256>>>(Wq, whi + 0 * (size_t)H_ * H_, wlo + 0 * (size_t)H_ * H_);
    cvt_kernel<<<(H_ * H_) / 1024, 256>>>(Wk, whi + 1 * (size_t)H_ * H_, wlo + 1 * (size_t)H_ * H_);
    cvt_kernel<<<(H_ * H_) / 1024, 256>>>(Wv, whi + 2 * (size_t)H_ * H_, wlo + 2 * (size_t)H_ * H_);
    cvt_kernel<<<(H_ * H_) / 1024, 256>>>(Wo, whi + 3 * (size_t)H_ * H_, wlo + 3 * (size_t)H_ * H_);

    proj_mma_kernel<<<dim3(H_ / 128, M_ / 128, 3), 256, GEMM_SMEM>>>(bq, bk, bv);
    vt_split_kernel<<<dim3(S_ / 32, HD_ / 32, BH_), 256>>>();
    scores_mma_kernel<<<dim3(S_ / 128, S_ / 128, BH_), 256, SC_SMEM>>>(probs);
    rsum_kernel<<<(BH_ * S_) / 256, 256>>>();
    ctx_mma_kernel<<<dim3(S_ / 128, BH_), 256, CTX_SMEM>>>(probs);
    outproj_mma_kernel<<<dim3(H_ / 128, M_ / 128), 256, GEMM_SMEM>>>(bo, hs, out);
}

// round 17
// speedup vs baseline: 1.9713x; 1.1204x over previous
#include <cuda_runtime.h>
#include <cuda_bf16.h>

// ---------------------------------------------------------------------------
// AttentionBlock. pproc == plain linear in fwd. B=4,S=2048,H=1024,NH=16,HD=64.
// Output = [out (B,S,H)] ++ [probs (B,NH,S,S)], fp32.
// R17: fused two-pass attention (scores+softmax+ctx in one kernel; probs
//      written exactly once). proj/outproj mma.sync as in R16.
// ---------------------------------------------------------------------------

namespace {
constexpr int B_  = 4;
constexpr int S_  = 2048;
constexpr int H_  = 1024;
constexpr int NH_ = 16;
constexpr int HD_ = 64;
constexpr int M_  = B_ * S_;
constexpr int BH_ = B_ * NH_;
constexpr long long OUT_ELEMS   = (long long)M_ * H_;
constexpr long long PROBS_ELEMS = (long long)BH_ * S_ * S_;

constexpr int GEMM_SMEM = 2 * 65536;      // proj/outproj: 2 x (Ahi|Alo|Bhi|Blo)

// fused attention smem layout (bytes from base)
constexpr unsigned A_SUM = 0;             // 128 floats (rowsum -> inv)
constexpr unsigned A_QHI = 512;           // 16 KB
constexpr unsigned A_QLO = 16896;         // 16 KB
constexpr unsigned A_K   = 33280;         // 2 bufs x (Khi 16K | Klo 16K)
constexpr unsigned A_V   = 98816;         // 2 bufs x (Vhi 16K | Vlo 16K), 2 subtiles each
constexpr unsigned A_PHI = 164352;        // 32 KB (2 subtiles of 16K)
constexpr unsigned A_PLO = 197120;        // 32 KB
constexpr int ATTN_SMEM  = 229888;
}

typedef unsigned long long u64;
typedef __nv_bfloat16 bf16;

// ---------------- scratch ---------------------------------------------------
__device__ bf16  g_xhi[M_ * H_],  g_xlo[M_ * H_];        // X split
__device__ bf16  g_whi[4 * H_ * H_], g_wlo[4 * H_ * H_]; // Wq,Wk,Wv,Wo split
__device__ bf16  g_qhi[M_ * H_], g_qlo[M_ * H_];         // [BH][S][HD]
__device__ bf16  g_khi[M_ * H_], g_klo[M_ * H_];         // [BH][S][HD]
__device__ float g_v[M_ * H_];                           // [BH][S][HD]
__device__ bf16  g_vthi[M_ * H_], g_vtlo[M_ * H_];       // [BH][HD][S]
__device__ bf16  g_chi[M_ * H_], g_clo[M_ * H_];         // ctx split [B,S,H]
__device__ float g_probs_fallback[268435456];

// ---------------- helpers ----------------------------------------------------
__device__ __forceinline__ unsigned smem_u32(const void* p) {
    unsigned a;
    asm("{ .reg .u64 t; cvta.to.shared.u64 t, %1; cvt.u32.u64 %0, t; }" : "=r"(a) : "l"(p));
    return a;
}
__device__ __forceinline__ unsigned sw128(unsigned off) { return off ^ ((off >> 3) & 0x70); }
__device__ __forceinline__ unsigned swadr(unsigned base, int row, int kbyte) {
    unsigned off = (unsigned)(row * 128 + kbyte);
    return base + (off ^ ((off >> 3) & 0x70));
}
__device__ __forceinline__ void ldsm4(unsigned r[4], unsigned addr) {
    asm volatile("ldmatrix.sync.aligned.m8n8.x4.shared.b16 {%0,%1,%2,%3}, [%4];"
        : "=r"(r[0]), "=r"(r[1]), "=r"(r[2]), "=r"(r[3]) : "r"(addr));
}
__device__ __forceinline__ void mma16816(float d[4], const unsigned a[4], const unsigned b[2]) {
    asm volatile(
        "mma.sync.aligned.m16n8k16.row.col.f32.bf16.bf16.f32 "
        "{%0,%1,%2,%3}, {%4,%5,%6,%7}, {%8,%9}, {%0,%1,%2,%3};"
        : "+f"(d[0]), "+f"(d[1]), "+f"(d[2]), "+f"(d[3])
        : "r"(a[0]), "r"(a[1]), "r"(a[2]), "r"(a[3]), "r"(b[0]), "r"(b[1]));
}
__device__ __forceinline__ void split1(float x, bf16& h, bf16& l) {
    h = __float2bfloat16(x);
    l = __float2bfloat16(x - __bfloat162float(h));
}
__device__ __forceinline__ void cpa16(unsigned dst, const void* src) {
    asm volatile("cp.async.cg.shared.global [%0], [%1], 16;" :: "r"(dst), "l"(src));
}
__device__ __forceinline__ void cpa_commit() {
    asm volatile("cp.async.commit_group;" ::: "memory");
}

// 3-term split S = Q K^T over one 128x128 tile (K=64). Warp computes 16 rows.
__device__ __forceinline__ void compute_S(
    float (&acc)[16][4], unsigned Qhi, unsigned Qlo, unsigned Khi, unsigned Klo,
    int r0, int lane)
{
    const int arow = r0 + (lane & 15);
    const int akb  = (lane >> 4) * 16;
    const int brow = (lane & 7) + ((lane >> 4) << 3);
    const int bkb  = ((lane >> 3) & 1) * 16;
#pragma unroll
    for (int k16 = 0; k16 < 4; k16++) {
        const int kb = k16 * 32;
        unsigned ah[4], al[4], bt[4][4];
        ldsm4(ah, swadr(Qhi, arow, kb + akb));
        ldsm4(al, swadr(Qlo, arow, kb + akb));
#pragma unroll
        for (int half = 0; half < 2; half++) {
            const int nb = half * 64;
#pragma unroll
            for (int t = 0; t < 4; t++) ldsm4(bt[t], swadr(Khi, nb + brow + t * 16, kb + bkb));
#pragma unroll
            for (int q = 0; q < 8; q++) mma16816(acc[half * 8 + q], ah, &bt[q >> 1][(q & 1) * 2]);
#pragma unroll
            for (int q = 0; q < 8; q++) mma16816(acc[half * 8 + q], al, &bt[q >> 1][(q & 1) * 2]);
#pragma unroll
            for (int t = 0; t < 4; t++) ldsm4(bt[t], swadr(Klo, nb + brow + t * 16, kb + bkb));
#pragma unroll
            for (int q = 0; q < 8; q++) mma16816(acc[half * 8 + q], ah, &bt[q >> 1][(q & 1) * 2]);
        }
    }
}

// ---------------- packed f32x2 (not used in GEMMs anymore; kept minimal) ----

// ---------------------------------------------------------------------------
// Kernel 0: fp32 -> (bf16 hi, lo) split.
// ---------------------------------------------------------------------------
__global__ void __launch_bounds__(256) cvt_kernel(const float* __restrict__ src,
    bf16* __restrict__ dh, bf16* __restrict__ dl)
{
    const int i = blockIdx.x * 256 + threadIdx.x;
    float4 v = ((const float4*)src)[i];
    union { bf16 b[4]; uint2 u; } Hh, Ll;
    split1(v.x, Hh.b[0], Ll.b[0]);
    split1(v.y, Hh.b[1], Ll.b[1]);
    split1(v.z, Hh.b[2], Ll.b[2]);
    split1(v.w, Hh.b[3], Ll.b[3]);
    ((uint2*)dh)[i] = Hh.u;
    ((uint2*)dl)[i] = Ll.u;
}

// ---------------------------------------------------------------------------
// Kernel 1: QKV projection (mma.sync). grid (8, 64, 3). 128x128, K=1024.
// ---------------------------------------------------------------------------
__device__ __forceinline__ void fill_tiles_cpa(unsigned sbase, int buf,
    const char* s0, const char* s1, const char* s2, const char* s3,
    int kb2, int tid)
{
    const char* srcs[4] = {s0, s1, s2, s3};
#pragma unroll
    for (int t = 0; t < 16; t++) {
        const int u = tid + t * 256;
        const int tt = u >> 10, w = u & 1023;
        const int r = w >> 3, sg = (w & 7) * 16;
        cpa16(sbase + buf * 65536 + tt * 16384 + sw128((unsigned)(r * 128 + sg)),
              srcs[tt] + (size_t)r * 2048 + kb2 + sg);
    }
    cpa_commit();
}

__global__ void __launch_bounds__(256) proj_mma_kernel(
    const float* __restrict__ bq, const float* __restrict__ bk,
    const float* __restrict__ bv)
{
    extern __shared__ char smem[];
    const int tid = threadIdx.x, lane = tid & 31, wid = tid >> 5;
    const int wm = wid & 3, wn = wid >> 2;
    const int sel = blockIdx.z;
    const int n0 = blockIdx.x * 128, m0 = blockIdx.y * 128;
    const unsigned sb = smem_u32(smem);

    const char* Ah = (const char*)g_xhi + (size_t)m0 * 2048;
    const char* Al = (const char*)g_xlo + (size_t)m0 * 2048;
    const char* Bh = (const char*)(g_whi + (size_t)sel * H_ * H_) + (size_t)n0 * 2048;
    const char* Bl = (const char*)(g_wlo + (size_t)sel * H_ * H_) + (size_t)n0 * 2048;

    float acc[2][8][4];
#pragma unroll
    for (int mt = 0; mt < 2; mt++)
#pragma unroll
        for (int nt = 0; nt < 8; nt++)
#pragma unroll
            for (int e = 0; e < 4; e++) acc[mt][nt][e] = 0.f;

    const int arow = wm * 32 + (lane & 15);
    const int akb  = (lane >> 4) * 16;
    const int brow = wn * 64 + (lane & 7) + ((lane >> 4) << 3);
    const int bkb  = ((lane >> 3) & 1) * 16;

    fill_tiles_cpa(sb, 0, Ah, Al, Bh, Bl, 0, tid);
    fill_tiles_cpa(sb, 1, Ah, Al, Bh, Bl, 128, tid);

    for (int c = 0; c < 16; c++) {
        if (c < 15) asm volatile("cp.async.wait_group 1;" ::: "memory");
        else        asm volatile("cp.async.wait_group 0;" ::: "memory");
        __syncthreads();

        const int b = c & 1;
        const unsigned Thi = sb + b * 65536;
        const unsigned Tlo = Thi + 16384, Tbh = Thi + 32768, Tbl = Thi + 49152;
#pragma unroll
        for (int k16 = 0; k16 < 4; k16++) {
            const int kb = k16 * 32;
            unsigned ah[2][4], al[2][4], bt[4][4];
            ldsm4(ah[0], swadr(Thi, arow,      kb + akb));
            ldsm4(ah[1], swadr(Thi, arow + 16, kb + akb));
            ldsm4(al[0], swadr(Tlo, arow,      kb + akb));
            ldsm4(al[1], swadr(Tlo, arow + 16, kb + akb));
#pragma unroll
            for (int t = 0; t < 4; t++) ldsm4(bt[t], swadr(Tbh, brow + t * 16, kb + bkb));
#pragma unroll
            for (int mt = 0; mt < 2; mt++)
#pragma unroll
                for (int nt = 0; nt < 8; nt++)
                    mma16816(acc[mt][nt], ah[mt], &bt[nt >> 1][(nt & 1) * 2]);
#pragma unroll
            for (int mt = 0; mt < 2; mt++)
#pragma unroll
                for (int nt = 0; nt < 8; nt++)
                    mma16816(acc[mt][nt], al[mt], &bt[nt >> 1][(nt & 1) * 2]);
#pragma unroll
            for (int t = 0; t < 4; t++) ldsm4(bt[t], swadr(Tbl, brow + t * 16, kb + bkb));
#pragma unroll
            for (int mt = 0; mt < 2; mt++)
#pragma unroll
                for (int nt = 0; nt < 8; nt++)
                    mma16816(acc[mt][nt], ah[mt], &bt[nt >> 1][(nt & 1) * 2]);
        }
        __syncthreads();
        if (c + 2 < 16)
            fill_tiles_cpa(sb, b, Ah, Al, Bh, Bl, (c + 2) * 128, tid);
    }

    const float* bias = (sel == 0) ? bq : (sel == 1) ? bk : bv;
    bf16* dh = (sel == 0) ? g_qhi : g_khi;
    bf16* dl = (sel == 0) ? g_qlo : g_klo;

#pragma unroll
    for (int mt = 0; mt < 2; mt++) {
        const int r0 = wm * 32 + mt * 16 + (lane >> 2);
#pragma unroll
        for (int nt = 0; nt < 8; nt++) {
            const int cc = wn * 64 + nt * 8 + (lane & 3) * 2;
            const int n = n0 + cc;
            const float b0 = bias[n], b1 = bias[n + 1];
            const int h = n >> 6, d = n & 63;
#pragma unroll
            for (int rh = 0; rh < 2; rh++) {
                const int m = m0 + r0 + rh * 8;
                const int bb = m >> 11, s = m & (S_ - 1);
                const float v0 = acc[mt][nt][rh * 2 + 0] + b0;
                const float v1 = acc[mt][nt][rh * 2 + 1] + b1;
                const size_t base = ((size_t)((bb << 4) + h) * S_ + s) * HD_ + d;
                if (sel < 2) {
                    bf16 h0, l0, h1, l1;
                    split1(v0, h0, l0); split1(v1, h1, l1);
                    __nv_bfloat162 hh; hh.x = h0; hh.y = h1;
                    __nv_bfloat162 ll; ll.x = l0; ll.y = l1;
                    *(__nv_bfloat162*)(dh + base) = hh;
                    *(__nv_bfloat162*)(dl + base) = ll;
                } else {
                    *(float2*)(g_v + base) = make_float2(v0, v1);
                }
            }
        }
    }
}

// ---------------------------------------------------------------------------
// Kernel 2: V transpose + bf16 split: [BH][S][HD] fp32 -> [BH][HD][S] hi/lo.
// ---------------------------------------------------------------------------
__global__ void __launch_bounds__(256) vt_split_kernel()
{
    __shared__ float t[32][33];
    const int tx = threadIdx.x & 31, ty = threadIdx.x >> 5;
    const int s0 = blockIdx.x * 32, d0 = blockIdx.y * 32, bh = blockIdx.z;
    const float* V = g_v + (size_t)bh * S_ * HD_;
#pragma unroll
    for (int i = 0; i < 4; i++)
        t[ty + i * 8][tx] = V[(size_t)(s0 + ty + i * 8) * HD_ + d0 + tx];
    __syncthreads();
    bf16* vh = g_vthi + ((size_t)bh * HD_) * S_;
    bf16* vl = g_vtlo + ((size_t)bh * HD_) * S_;
#pragma unroll
    for (int i = 0; i < 4; i++) {
        const int d = d0 + ty + i * 8;
        bf16 h, l;
        split1(t[tx][ty + i * 8], h, l);
        vh[(size_t)d * S_ + s0 + tx] = h;
        vl[(size_t)d * S_ + s0 + tx] = l;
    }
}

// ---------------------------------------------------------------------------
// Kernel 3: fused attention. grid (16 m-tiles, 64 bh). 256 thr, 8 warps;
// each warp owns 16 rows. Pass A: rowsums. Pass B: recompute, normalize,
// write probs once, accumulate ctx. K/V cp.async double-buffered.
// ---------------------------------------------------------------------------
__global__ void __launch_bounds__(256) attn_fused_kernel(float* __restrict__ probs)
{
    extern __shared__ char smem[];
    const int tid = threadIdx.x, lane = tid & 31, wid = tid >> 5;
    const int r0 = wid * 16;
    const int m0 = blockIdx.x * 128, bh = blockIdx.y;
    const unsigned sb = smem_u32(smem);

    const char* gqh = (const char*)g_qhi + (size_t)(bh * S_ + m0) * 128;
    const char* gql = (const char*)g_qlo + (size_t)(bh * S_ + m0) * 128;
    const char* gkh = (const char*)g_khi + (size_t)bh * S_ * 128;
    const char* gkl = (const char*)g_klo + (size_t)bh * S_ * 128;
    const char* gvh = (const char*)g_vthi + (size_t)bh * HD_ * S_ * 2;
    const char* gvl = (const char*)g_vtlo + (size_t)bh * HD_ * S_ * 2;

    // Q fill (one group)
#pragma unroll
    for (int t = 0; t < 8; t++) {
        const int u = tid + t * 256;
        const int half = u >> 10, w = u & 1023;
        const int r = w >> 3, sg = (w & 7) * 16;
        cpa16(sb + (half ? A_QLO : A_QHI) + sw128((unsigned)(r * 128 + sg)),
              (half ? gql : gqh) + (size_t)r * 128 + sg);
    }
    cpa_commit();

#define FILL_K(kt, b) do {                                                  \
    const size_t tb = (size_t)(kt) * 16384;                                 \
    _Pragma("unroll")                                                       \
    for (int t = 0; t < 8; t++) {                                           \
        const int u = tid + t * 256;                                        \
        const int half = u >> 10, w = u & 1023;                             \
        const int r = w >> 3, sg = (w & 7) * 16;                            \
        cpa16(sb + A_K + (b) * 32768 + half * 16384 + sw128((unsigned)(r * 128 + sg)), \
              (half ? gkl : gkh) + tb + (size_t)r * 128 + sg);              \
    }                                                                       \
    cpa_commit();                                                           \
} while (0)

#define FILL_KV(kt, b) do {                                                 \
    const size_t tb = (size_t)(kt) * 16384;                                 \
    _Pragma("unroll")                                                       \
    for (int t = 0; t < 8; t++) {                                           \
        const int u = tid + t * 256;                                        \
        const int half = u >> 10, w = u & 1023;                             \
        const int r = w >> 3, sg = (w & 7) * 16;                            \
        cpa16(sb + A_K + (b) * 32768 + half * 16384 + sw128((unsigned)(r * 128 + sg)), \
              (half ? gkl : gkh) + tb + (size_t)r * 128 + sg);              \
    }                                                                       \
    _Pragma("unroll")                                                       \
    for (int t = 0; t < 8; t++) {                                           \
        const int u = tid + t * 256;                                        \
        const int half = u >> 10, w = u & 1023;                             \
        const int sub = (w >> 9) & 1;                                       \
        const int r = (w >> 3) & 63, sg = (w & 7) * 16;                     \
        cpa16(sb + A_V + (b) * 32768 + half * 16384 + sub * 8192 + sw128((unsigned)(r * 128 + sg)), \
              (half ? gvl : gvh) + (size_t)r * (S_ * 2) + (size_t)(kt) * 256 + sub * 128 + sg); \
    }                                                                       \
    cpa_commit();                                                           \
} while (0)

    // ---------------- pass A: rowsums ----------------
    FILL_K(0, 0);
    FILL_K(1, 1);

    float rs0 = 0.f, rs1 = 0.f;
    for (int c = 0; c < 16; c++) {
        if (c < 15) asm volatile("cp.async.wait_group 1;" ::: "memory");
        else        asm volatile("cp.async.wait_group 0;" ::: "memory");
        __syncthreads();
        const int b = c & 1;
        float acc[16][4];
#pragma unroll
        for (int nt = 0; nt < 16; nt++)
#pragma unroll
            for (int e = 0; e < 4; e++) acc[nt][e] = 0.f;
        compute_S(acc, sb + A_QHI, sb + A_QLO,
                  sb + A_K + b * 32768, sb + A_K + b * 32768 + 16384, r0, lane);
#pragma unroll
        for (int nt = 0; nt < 16; nt++) {
            rs0 += __expf(acc[nt][0] - 12.f) + __expf(acc[nt][1] - 12.f);
            rs1 += __expf(acc[nt][2] - 12.f) + __expf(acc[nt][3] - 12.f);
        }
        __syncthreads();
        if (c + 2 < 16) FILL_K(c + 2, b);
    }

    // reduce rowsums -> s_sum, then invert in place
    rs0 += __shfl_xor_sync(0xffffffffu, rs0, 1);
    rs0 += __shfl_xor_sync(0xffffffffu, rs0, 2);
    rs1 += __shfl_xor_sync(0xffffffffu, rs1, 1);
    rs1 += __shfl_xor_sync(0xffffffffu, rs1, 2);
    float* s_sum = (float*)smem;
    __syncthreads();                    // all warps done with pass A buffers
    if ((lane & 3) == 0) {
        s_sum[r0 + (lane >> 2)]     = rs0;
        s_sum[r0 + 8 + (lane >> 2)] = rs1;
    }
    // prefetch pass B tiles while reducing
    FILL_KV(0, 0);
    FILL_KV(1, 1);
    __syncthreads();
    if (tid < 128) s_sum[tid] = 1.0f / s_sum[tid];
    __syncthreads();

    // ---------------- pass B: normalize, write probs, ctx ----------------
    float accc[8][4];
#pragma unroll
    for (int q = 0; q < 8; q++)
#pragma unroll
        for (int e = 0; e < 4; e++) accc[q][e] = 0.f;

    const float iv0 = s_sum[r0 + (lane >> 2)];
    const float iv1 = s_sum[r0 + 8 + (lane >> 2)];
    const int rrow0 = r0 + (lane >> 2), rrow1 = rrow0 + 8;
    float* P = probs + (size_t)bh * S_ * S_;

    for (int c = 0; c < 16; c++) {
        if (c < 15) asm volatile("cp.async.wait_group 1;" ::: "memory");
        else        asm volatile("cp.async.wait_group 0;" ::: "memory");
        __syncthreads();
        const int b = c & 1;

        float acc[16][4];
#pragma unroll
        for (int nt = 0; nt < 16; nt++)
#pragma unroll
            for (int e = 0; e < 4; e++) acc[nt][e] = 0.f;
        compute_S(acc, sb + A_QHI, sb + A_QLO,
                  sb + A_K + b * 32768, sb + A_K + b * 32768 + 16384, r0, lane);

        // exp, normalize, split -> P smem (warp-local rows)
#pragma unroll
        for (int nt = 0; nt < 16; nt++) {
            const float p0 = __expf(acc[nt][0] - 12.f) * iv0;
            const float p1 = __expf(acc[nt][1] - 12.f) * iv0;
            const float p2 = __expf(acc[nt][2] - 12.f) * iv1;
            const float p3 = __expf(acc[nt][3] - 12.f) * iv1;
            const int cc = nt * 8 + (lane & 3) * 2;
            const int sub = cc >> 6, cs2 = (cc & 63) * 2;
            bf16 h0, l0, h1, l1;
            split1(p0, h0, l0); split1(p1, h1, l1);
            __nv_bfloat162 hh; hh.x = h0; hh.y = h1;
            __nv_bfloat162 ll; ll.x = l0; ll.y = l1;
            *(__nv_bfloat162*)(smem + A_PHI + sub * 16384 + sw128((unsigned)(rrow0 * 128 + cs2))) = hh;
            *(__nv_bfloat162*)(smem + A_PLO + sub * 16384 + sw128((unsigned)(rrow0 * 128 + cs2))) = ll;
            split1(p2, h0, l0); split1(p3, h1, l1);
            hh.x = h0; hh.y = h1; ll.x = l0; ll.y = l1;
            *(__nv_bfloat162*)(smem + A_PHI + sub * 16384 + sw128((unsigned)(rrow1 * 128 + cs2))) = hh;
            *(__nv_bfloat162*)(smem + A_PLO + sub * 16384 + sw128((unsigned)(rrow1 * 128 + cs2))) = ll;
        }
        __syncwarp();

        // probs write: coalesced, warp-local rows (fp32 = hi + lo)
        {
            const int sub = lane >> 4;
            const int cs2 = (lane & 15) * 8;
#pragma unroll
            for (int i = 0; i < 16; i++) {
                const int row = r0 + i;
                const unsigned ao = sub * 16384 + sw128((unsigned)(row * 128 + cs2));
                uint2 uh = *(uint2*)(smem + A_PHI + ao);
                uint2 ul = *(uint2*)(smem + A_PLO + ao);
                __nv_bfloat162 h01 = *(__nv_bfloat162*)&uh.x;
                __nv_bfloat162 h23 = *(__nv_bfloat162*)&uh.y;
                __nv_bfloat162 l01 = *(__nv_bfloat162*)&ul.x;
                __nv_bfloat162 l23 = *(__nv_bfloat162*)&ul.y;
                float4 o;
                o.x = __bfloat162float(h01.x) + __bfloat162float(l01.x);
                o.y = __bfloat162float(h01.y) + __bfloat162float(l01.y);
                o.z = __bfloat162float(h23.x) + __bfloat162float(l23.x);
                o.w = __bfloat162float(h23.y) + __bfloat162float(l23.y);
                *(float4*)(P + (size_t)(m0 + row) * S_ + c * 128 + lane * 4) = o;
            }
        }

        // ctx accumulate: accc += Pnorm @ V (3-term)
        {
            const int arow = r0 + (lane & 15);
            const int akb  = (lane >> 4) * 16;
            const int brow = (lane & 7) + ((lane >> 4) << 3);
            const int bkb  = ((lane >> 3) & 1) * 16;
#pragma unroll
            for (int k16 = 0; k16 < 8; k16++) {
                const int sub = k16 >> 2, kb = (k16 & 3) * 32;
                unsigned ph[4], pl[4], bt[4][4];
                ldsm4(ph, swadr(sb + A_PHI + sub * 16384, arow, kb + akb));
                ldsm4(pl, swadr(sb + A_PLO + sub * 16384, arow, kb + akb));
#pragma unroll
                for (int t = 0; t < 4; t++)
                    ldsm4(bt[t], swadr(sb + A_V + b * 32768 + sub * 8192, brow + t * 16, kb + bkb));
#pragma unroll
                for (int q = 0; q < 8; q++) mma16816(accc[q], ph, &bt[q >> 1][(q & 1) * 2]);
#pragma unroll
                for (int q = 0; q < 8; q++) mma16816(accc[q], pl, &bt[q >> 1][(q & 1) * 2]);
#pragma unroll
                for (int t = 0; t < 4; t++)
                    ldsm4(bt[t], swadr(sb + A_V + b * 32768 + 16384 + sub * 8192, brow + t * 16, kb + bkb));
#pragma unroll
                for (int q = 0; q < 8; q++) mma16816(accc[q], ph, &bt[q >> 1][(q & 1) * 2]);
            }
        }
        __syncthreads();
        if (c + 2 < 16) FILL_KV(c + 2, b);
    }
#undef FILL_K
#undef FILL_KV

    // epilogue: ctx -> split bf16 [B,S,H]
    const int bb = bh >> 4, hh = bh & 15;
#pragma unroll
    for (int q = 0; q < 8; q++) {
        const int cc = q * 8 + (lane & 3) * 2;
#pragma unroll
        for (int rh = 0; rh < 2; rh++) {
            const int r = (rh ? rrow1 : rrow0);
            const float v0 = accc[q][rh * 2 + 0];
            const float v1 = accc[q][rh * 2 + 1];
            bf16 h0, l0, h1, l1;
            split1(v0, h0, l0); split1(v1, h1, l1);
            __nv_bfloat162 hhv; hhv.x = h0; hhv.y = h1;
            __nv_bfloat162 llv; llv.x = l0; llv.y = l1;
            const size_t dst = ((size_t)(bb * S_ + m0 + r)) * H_ + hh * HD_ + cc;
            *(__nv_bfloat162*)(g_chi + dst) = hhv;
            *(__nv_bfloat162*)(g_clo + dst) = llv;
        }
    }
}

// ---------------------------------------------------------------------------
// Kernel 4: out = ctx @ Wo.T + bo + hidden (mma.sync). grid (8, 64).
// ---------------------------------------------------------------------------
__global__ void __launch_bounds__(256) outproj_mma_kernel(
    const float* __restrict__ bias,
    const float* __restrict__ hid,
    float* __restrict__ out)
{
    extern __shared__ char smem[];
    const int tid = threadIdx.x, lane = tid & 31, wid = tid >> 5;
    const int wm = wid & 3, wn = wid >> 2;
    const int n0 = blockIdx.x * 128, m0 = blockIdx.y * 128;
    const unsigned sb = smem_u32(smem);

    const char* Ah = (const char*)g_chi + (size_t)m0 * 2048;
    const char* Al = (const char*)g_clo + (size_t)m0 * 2048;
    const char* Bh = (const char*)(g_whi + (size_t)3 * H_ * H_) + (size_t)n0 * 2048;
    const char* Bl = (const char*)(g_wlo + (size_t)3 * H_ * H_) + (size_t)n0 * 2048;

    float acc[2][8][4];
#pragma unroll
    for (int mt = 0; mt < 2; mt++)
#pragma unroll
        for (int nt = 0; nt < 8; nt++)
#pragma unroll
            for (int e = 0; e < 4; e++) acc[mt][nt][e] = 0.f;

    const int arow = wm * 32 + (lane & 15);
    const int akb  = (lane >> 4) * 16;
    const int brow = wn * 64 + (lane & 7) + ((lane >> 4) << 3);
    const int bkb  = ((lane >> 3) & 1) * 16;

    fill_tiles_cpa(sb, 0, Ah, Al, Bh, Bl, 0, tid);
    fill_tiles_cpa(sb, 1, Ah, Al, Bh, Bl, 128, tid);

    for (int c = 0; c < 16; c++) {
        if (c < 15) asm volatile("cp.async.wait_group 1;" ::: "memory");
        else        asm volatile("cp.async.wait_group 0;" ::: "memory");
        __syncthreads();

        const int b = c & 1;
        const unsigned Thi = sb + b * 65536;
        const unsigned Tlo = Thi + 16384, Tbh = Thi + 32768, Tbl = Thi + 49152;
#pragma unroll
        for (int k16 = 0; k16 < 4; k16++) {
            const int kb = k16 * 32;
            unsigned ah[2][4], al[2][4], bt[4][4];
            ldsm4(ah[0], swadr(Thi, arow,      kb + akb));
            ldsm4(ah[1], swadr(Thi, arow + 16, kb + akb));
            ldsm4(al[0], swadr(Tlo, arow,      kb + akb));
            ldsm4(al[1], swadr(Tlo, arow + 16, kb + akb));
#pragma unroll
            for (int t = 0; t < 4; t++) ldsm4(bt[t], swadr(Tbh, brow + t * 16, kb + bkb));
#pragma unroll
            for (int mt = 0; mt < 2; mt++)
#pragma unroll
                for (int nt = 0; nt < 8; nt++)
                    mma16816(acc[mt][nt], ah[mt], &bt[nt >> 1][(nt & 1) * 2]);
#pragma unroll
            for (int mt = 0; mt < 2; mt++)
#pragma unroll
                for (int nt = 0; nt < 8; nt++)
                    mma16816(acc[mt][nt], al[mt], &bt[nt >> 1][(nt & 1) * 2]);
#pragma unroll
            for (int t = 0; t < 4; t++) ldsm4(bt[t], swadr(Tbl, brow + t * 16, kb + bkb));
#pragma unroll
            for (int mt = 0; mt < 2; mt++)
#pragma unroll
                for (int nt = 0; nt < 8; nt++)
                    mma16816(acc[mt][nt], ah[mt], &bt[nt >> 1][(nt & 1) * 2]);
        }
        __syncthreads();
        if (c + 2 < 16)
            fill_tiles_cpa(sb, b, Ah, Al, Bh, Bl, (c + 2) * 128, tid);
    }

#pragma unroll
    for (int mt = 0; mt < 2; mt++) {
        const int r0 = wm * 32 + mt * 16 + (lane >> 2);
#pragma unroll
        for (int nt = 0; nt < 8; nt++) {
            const int cc = wn * 64 + nt * 8 + (lane & 3) * 2;
            const int n = n0 + cc;
            const float b0 = bias[n], b1 = bias[n + 1];
#pragma unroll
            for (int rh = 0; rh < 2; rh++) {
                const int m = m0 + r0 + rh * 8;
                const float2 hh = *(const float2*)(hid + (size_t)m * H_ + n);
                float2 v;
                v.x = acc[mt][nt][rh * 2 + 0] + b0 + hh.x;
                v.y = acc[mt][nt][rh * 2 + 1] + b1 + hh.y;
                *(float2*)(out + (size_t)m * H_ + n) = v;
            }
        }
    }
}

// ---------------------------------------------------------------------------
extern "C" void kernel_launch(void* const* d_in, const int* in_sizes, int n_in,
                              void* d_out, int out_size)
{
    (void)in_sizes; (void)n_in;

    const float* hs = (const float*)d_in[0];
    const float* Wq = (const float*)d_in[1];
    const float* bq = (const float*)d_in[2];
    const float* Wk = (const float*)d_in[3];
    const float* bk = (const float*)d_in[4];
    const float* Wv = (const float*)d_in[5];
    const float* bv = (const float*)d_in[6];
    const float* Wo = (const float*)d_in[7];
    const float* bo = (const float*)d_in[8];
    float* out = (float*)d_out;

    float* probs;
    if ((long long)out_size >= OUT_ELEMS + PROBS_ELEMS) {
        probs = out + OUT_ELEMS;
    } else {
        void* p = nullptr;
        cudaGetSymbolAddress(&p, g_probs_fallback);
        probs = (float*)p;
    }

    bf16 *xhi, *xlo, *whi, *wlo;
    { void* p; cudaGetSymbolAddress(&p, g_xhi); xhi = (bf16*)p; }
    { void* p; cudaGetSymbolAddress(&p, g_xlo); xlo = (bf16*)p; }
    { void* p; cudaGetSymbolAddress(&p, g_whi); whi = (bf16*)p; }
    { void* p; cudaGetSymbolAddress(&p, g_wlo); wlo = (bf16*)p; }

    cudaFuncSetAttribute(proj_mma_kernel,    cudaFuncAttributeMaxDynamicSharedMemorySize, GEMM_SMEM);
    cudaFuncSetAttribute(outproj_mma_kernel, cudaFuncAttributeMaxDynamicSharedMemorySize, GEMM_SMEM);
    cudaFuncSetAttribute(attn_fused_kernel,  cudaFuncAttributeMaxDynamicSharedMemorySize, ATTN_SMEM);

    cvt_kernel<<<(M_ * H_) / 1024, 256>>>(hs, xhi, xlo);
    cvt_kernel<<<(H_ * H_) / 1024, 256>>>(Wq, whi + 0 * (size_t)H_ * H_, wlo + 0 * (size_t)H_ * H_);
    cvt_kernel<<<(H_ * H_) / 1024, 256>>>(Wk, whi + 1 * (size_t)H_ * H_, wlo + 1 * (size_t)H_ * H_);
    cvt_kernel<<<(H_ * H_) / 1024, 256>>>(Wv, whi + 2 * (size_t)H_ * H_, wlo + 2 * (size_t)H_ * H_);
    cvt_kernel<<<(H_ * H_) / 1024, 256>>>(Wo, whi + 3 * (size_t)H_ * H_, wlo + 3 * (size_t)H_ * H_);

    proj_mma_kernel<<<dim3(H_ / 128, M_ / 128, 3), 256, GEMM_SMEM>>>(bq, bk, bv);
    vt_split_kernel<<<dim3(S_ / 32, HD_ / 32, BH_), 256>>>();
    attn_fused_kernel<<<dim3(S_ / 128, BH_), 256, ATTN_SMEM>>>(probs);
    outproj_mma_kernel<<<dim3(H_ / 128, M_ / 128), 256, GEMM_SMEM>>>(bo, hs, out);
}